// round 5
// baseline (speedup 1.0000x reference)
#include <cuda_runtime.h>
#include <cuda_bf16.h>
#include <math.h>

typedef unsigned long long ull;
typedef unsigned int uint;
typedef unsigned short ushort;

// Problem constants
#define BATCH 1024
#define TT    256
#define II    153
#define KP0   160        // II padded to multiple of 16
#define HH    128
#define G3    384
#define MTOT  (BATCH*TT)   // 262144

// ---------------------------------------------------------------------------
// Scratch (device globals — no runtime allocation allowed)
// ---------------------------------------------------------------------------
__device__ float g_gi[(size_t)MTOT * G3];                 // ~403 MB
__device__ __nv_bfloat16 g_xh[(size_t)MTOT * KP0];        // 84 MB
__device__ __nv_bfloat16 g_xl[(size_t)MTOT * KP0];        // 84 MB
__device__ __nv_bfloat16 g_sh[(size_t)MTOT * HH];         // 67 MB (seq hi)
__device__ __nv_bfloat16 g_sl[(size_t)MTOT * HH];         // 67 MB (seq lo)
__device__ __nv_bfloat16 g_w0h[G3 * KP0], g_w0l[G3 * KP0];
__device__ __nv_bfloat16 g_w1h[G3 * HH],  g_w1l[G3 * HH];
__device__ float g_hlast[BATCH * HH];

// ---------------------------------------------------------------------------
// f32x2 packed math (GRU kernel)
// ---------------------------------------------------------------------------
__device__ __forceinline__ ull pack2(float x, float y) {
    ull r; asm("mov.b64 %0, {%1, %2};" : "=l"(r) : "f"(x), "f"(y)); return r;
}
__device__ __forceinline__ void unpack2(ull v, float& x, float& y) {
    asm("mov.b64 {%0, %1}, %2;" : "=f"(x), "=f"(y) : "l"(v));
}
__device__ __forceinline__ ull fma2(ull a, ull b, ull c) {
    ull d; asm("fma.rn.f32x2 %0, %1, %2, %3;" : "=l"(d) : "l"(a), "l"(b), "l"(c));
    return d;
}

// ---------------------------------------------------------------------------
// bf16 split + tensor-core helpers
// ---------------------------------------------------------------------------
__device__ __forceinline__ void split_bf16(float a, __nv_bfloat16& h, __nv_bfloat16& l) {
    h = __float2bfloat16(a);
    l = __float2bfloat16(a - __bfloat162float(h));
}
__device__ __forceinline__ void ldsm_x4(uint& r0, uint& r1, uint& r2, uint& r3, uint addr) {
    asm volatile("ldmatrix.sync.aligned.m8n8.x4.shared.b16 {%0,%1,%2,%3}, [%4];"
        : "=r"(r0), "=r"(r1), "=r"(r2), "=r"(r3) : "r"(addr));
}
__device__ __forceinline__ void mma_bf16(float* d, const uint* a, const uint* b) {
    asm volatile("mma.sync.aligned.m16n8k16.row.col.f32.bf16.bf16.f32 "
        "{%0,%1,%2,%3}, {%4,%5,%6,%7}, {%8,%9}, {%0,%1,%2,%3};"
        : "+f"(d[0]), "+f"(d[1]), "+f"(d[2]), "+f"(d[3])
        : "r"(a[0]), "r"(a[1]), "r"(a[2]), "r"(a[3]), "r"(b[0]), "r"(b[1]));
}
__device__ __forceinline__ void cp16(uint dst, const void* src) {
    asm volatile("cp.async.cg.shared.global [%0], [%1], 16;" :: "r"(dst), "l"(src));
}
#define CP_COMMIT() asm volatile("cp.async.commit_group;")
#define CP_WAIT0()  asm volatile("cp.async.wait_group 0;")

// ---------------------------------------------------------------------------
// Prepass: split fp32 [rows,Kin] -> bf16 hi/lo [rows,Kout] (zero pad)
// ---------------------------------------------------------------------------
__global__ void prep_split(const float* __restrict__ in,
                           __nv_bfloat16* __restrict__ oh,
                           __nv_bfloat16* __restrict__ ol,
                           int rows, int Kin, int Kout)
{
    size_t total = (size_t)rows * Kout;
    for (size_t i = (size_t)blockIdx.x * blockDim.x + threadIdx.x; i < total;
         i += (size_t)gridDim.x * blockDim.x) {
        int k = (int)(i % Kout);
        size_t r = i / Kout;
        float v = (k < Kin) ? in[r * Kin + k] : 0.f;
        __nv_bfloat16 h, l;
        split_bf16(v, h, l);
        oh[i] = h;
        ol[i] = l;
    }
}

// ---------------------------------------------------------------------------
// Pure-bf16 tensor-core GEMM, 3-term split accumulation:
//   C[M,384] = (Ah+Al)[M,K] @ (Bh+Bl)[384,K]^T + bias  (Al*Bl dropped)
// CTA tile 128x128, 8 warps (2m x 4n), K multiple of 16, cp.async pipeline.
// smem rows: 16 hi halfs | 16 lo halfs | 8 pad (TLD=40) -> ldsm conflict-free.
// ---------------------------------------------------------------------------
#define TLD 40

__global__ __launch_bounds__(256, 2)
void gemm_tc2(const __nv_bfloat16* __restrict__ Ah, const __nv_bfloat16* __restrict__ Al,
              const __nv_bfloat16* __restrict__ Bh, const __nv_bfloat16* __restrict__ Bl,
              const float* __restrict__ bias, float* __restrict__ C, int K)
{
    __shared__ __align__(16) ushort sa[2][128 * TLD];
    __shared__ __align__(16) ushort sb[2][128 * TLD];

    const int tid  = threadIdx.x;
    const int warp = tid >> 5;
    const int lane = tid & 31;
    const size_t m0 = (size_t)blockIdx.x * 128;
    const int n0 = blockIdx.y * 128;
    const int wm = (warp >> 2) * 64;
    const int wn = (warp & 3) * 32;

    // cp.async seg decode (4 segs/thread, 1024 segs/tile):
    //   s = tid + 256*i ; mat = s>>9 (0=A,1=B); r = (s>>2)&127; seg = s&3
    //   seg 0,1 -> hi halves, seg 2,3 -> lo halves; dst byte = r*80 + seg*16
    const uint sa0 = (uint)__cvta_generic_to_shared(&sa[0][0]);
    const uint sb0 = (uint)__cvta_generic_to_shared(&sb[0][0]);
    const uint bufstride = 128 * TLD * 2;   // bytes per buffer

    float acc[4][4][4];
#pragma unroll
    for (int i = 0; i < 4; i++)
#pragma unroll
        for (int j = 0; j < 4; j++)
#pragma unroll
            for (int v = 0; v < 4; v++) acc[i][j][v] = 0.f;

    const int KT = K >> 4;

    // per-thread precomputed seg info
    const __nv_bfloat16* srcs[4];
    uint dsts[4];
    size_t srcoff[4];
#pragma unroll
    for (int i = 0; i < 4; i++) {
        int s   = tid + 256 * i;
        int mat = s >> 9;
        int r   = (s >> 2) & 127;
        int seg = s & 3;
        const __nv_bfloat16* base =
            mat ? (seg < 2 ? Bh : Bl) : (seg < 2 ? Ah : Al);
        size_t row = mat ? (size_t)(n0 + r) : (m0 + r);
        srcs[i]   = base;
        srcoff[i] = row * K + (seg & 1) * 8;
        dsts[i]   = (mat ? sb0 : sa0) + (uint)(r * 80 + seg * 16);
    }

    // prologue: tile 0 -> buf 0
#pragma unroll
    for (int i = 0; i < 4; i++)
        cp16(dsts[i], srcs[i] + srcoff[i]);
    CP_COMMIT();

    int buf = 0;
    for (int kt = 0; kt < KT; kt++) {
        CP_WAIT0();
        __syncthreads();

        if (kt + 1 < KT) {
            uint doff = (buf ^ 1) * bufstride;
            size_t koff = (size_t)(kt + 1) * 16;
#pragma unroll
            for (int i = 0; i < 4; i++)
                cp16(dsts[i] + doff, srcs[i] + srcoff[i] + koff);
            CP_COMMIT();
        }

        uint sa_base = sa0 + buf * bufstride;
        uint sb_base = sb0 + buf * bufstride;

        uint bhf[8], blf[8];
#pragma unroll
        for (int g = 0; g < 2; g++) {
            int nrow = wn + g * 16 + ((lane & 16) >> 1) + (lane & 7);
            int kcol = ((lane >> 3) & 1) * 8;
            ldsm_x4(bhf[g*4+0], bhf[g*4+1], bhf[g*4+2], bhf[g*4+3],
                    sb_base + (uint)(nrow * TLD + kcol) * 2u);
            ldsm_x4(blf[g*4+0], blf[g*4+1], blf[g*4+2], blf[g*4+3],
                    sb_base + (uint)(nrow * TLD + 16 + kcol) * 2u);
        }

#pragma unroll
        for (int mi = 0; mi < 4; mi++) {
            int arow = wm + mi * 16 + (lane & 15);
            int acol = ((lane >> 4) & 1) * 8;
            uint ah[4], al[4];
            ldsm_x4(ah[0], ah[1], ah[2], ah[3],
                    sa_base + (uint)(arow * TLD + acol) * 2u);
            ldsm_x4(al[0], al[1], al[2], al[3],
                    sa_base + (uint)(arow * TLD + 16 + acol) * 2u);
#pragma unroll
            for (int ni = 0; ni < 4; ni++) {
                mma_bf16(acc[mi][ni], ah, &bhf[ni*2]);
                mma_bf16(acc[mi][ni], ah, &blf[ni*2]);
                mma_bf16(acc[mi][ni], al, &bhf[ni*2]);
            }
        }
        buf ^= 1;
    }

    const int r = lane >> 2;
    const int c2 = (lane & 3) * 2;
#pragma unroll
    for (int mi = 0; mi < 4; mi++) {
#pragma unroll
        for (int ni = 0; ni < 4; ni++) {
            int n = n0 + wn + ni * 8 + c2;
            float b0 = bias[n], b1 = bias[n + 1];
            size_t m = m0 + wm + mi * 16 + r;
            float2 v0 = { acc[mi][ni][0] + b0, acc[mi][ni][1] + b1 };
            float2 v1 = { acc[mi][ni][2] + b0, acc[mi][ni][3] + b1 };
            *(float2*)&C[m * G3 + n]       = v0;
            *(float2*)&C[(m + 8) * G3 + n] = v1;
        }
    }
}

// ---------------------------------------------------------------------------
// GRU recurrence — W_hh in registers (R4, proven). Layer 0 writes seq as
// bf16 hi/lo splits directly (feeds the pure-bf16 layer-1 GEMM).
// ---------------------------------------------------------------------------
#define NB 8
#define NTH 384

__global__ __launch_bounds__(NTH)
void gru_layer(const float* __restrict__ gi,     // [B*T, 384]
               const float* __restrict__ W_hh,   // [384, 128]
               const float* __restrict__ b_hh,   // [384]
               __nv_bfloat16* __restrict__ seqh, // [B*T, 128] (layer 0)
               __nv_bfloat16* __restrict__ seql,
               float* __restrict__ hlast_out,    // [B, 128]   (layer 1)
               int write_seq)
{
    __shared__ float hs[NB][HH];
    __shared__ float rb[NB][HH];
    __shared__ float zb[NB][HH];

    const int gid = threadIdx.x;
    const int b0  = blockIdx.x * NB;
    const int j   = gid & 127;
    const int gtype = gid >> 7;

    ull Wp[64];
#pragma unroll
    for (int i = 0; i < 64; i++) {
        float2 w = *(const float2*)&W_hh[(size_t)gid * HH + 2 * i];
        Wp[i] = pack2(w.x, w.y);
    }

    for (int i = gid; i < NB * HH; i += NTH) (&hs[0][0])[i] = 0.f;
    const float bh = b_hh[gid];
    __syncthreads();

    for (int t = 0; t < TT; t++) {
        float giv[NB];
#pragma unroll
        for (int b = 0; b < NB; b++)
            giv[b] = gi[((size_t)((b0 + b) * TT + t)) * G3 + gid];

        ull acc[NB];
        const ull zz = pack2(0.f, 0.f);
#pragma unroll
        for (int b = 0; b < NB; b++) acc[b] = zz;

#pragma unroll
        for (int c = 0; c < 32; c++) {
#pragma unroll
            for (int b = 0; b < NB; b++) {
                ulonglong2 hv = *(const ulonglong2*)&hs[b][4 * c];
                acc[b] = fma2(Wp[2 * c],     hv.x, acc[b]);
                acc[b] = fma2(Wp[2 * c + 1], hv.y, acc[b]);
            }
        }

        float gh[NB];
#pragma unroll
        for (int b = 0; b < NB; b++) {
            float x, y; unpack2(acc[b], x, y);
            gh[b] = x + y + bh;
        }

        if (gtype == 0) {
#pragma unroll
            for (int b = 0; b < NB; b++)
                rb[b][j] = 1.f / (1.f + expf(-(giv[b] + gh[b])));
        } else if (gtype == 1) {
#pragma unroll
            for (int b = 0; b < NB; b++)
                zb[b][j] = 1.f / (1.f + expf(-(giv[b] + gh[b])));
        }
        __syncthreads();

        if (gtype == 2) {
#pragma unroll
            for (int b = 0; b < NB; b++) {
                float r = rb[b][j];
                float z = zb[b][j];
                float n = tanhf(giv[b] + r * gh[b]);
                float hn = (1.f - z) * n + z * hs[b][j];
                hs[b][j] = hn;
                if (write_seq) {
                    __nv_bfloat16 hh, hl;
                    split_bf16(hn, hh, hl);
                    size_t m = (size_t)((b0 + b) * TT + t) * HH + j;
                    seqh[m] = hh;
                    seql[m] = hl;
                }
            }
        }
        __syncthreads();
    }

    if (!write_seq && gtype == 2) {
#pragma unroll
        for (int b = 0; b < NB; b++)
            hlast_out[(b0 + b) * HH + j] = hs[b][j];
    }
}

// ---------------------------------------------------------------------------
// head — Linear(128,64) -> ReLU -> Linear(64,1) -> Sigmoid
// ---------------------------------------------------------------------------
__global__ __launch_bounds__(64)
void head_kernel(const float* __restrict__ hlast, const float* __restrict__ W1,
                 const float* __restrict__ b1, const float* __restrict__ W2,
                 const float* __restrict__ b2, float* __restrict__ out)
{
    __shared__ float hsm[HH];
    __shared__ float partial[2];
    const int b = blockIdx.x, tid = threadIdx.x;

    hsm[tid]      = hlast[b * HH + tid];
    hsm[tid + 64] = hlast[b * HH + 64 + tid];
    __syncthreads();

    float acc = b1[tid];
#pragma unroll 4
    for (int k = 0; k < HH; k++)
        acc += hsm[k] * W1[tid * HH + k];
    float v = fmaxf(acc, 0.f) * W2[tid];

#pragma unroll
    for (int o = 16; o > 0; o >>= 1)
        v += __shfl_down_sync(0xffffffffu, v, o);
    if ((tid & 31) == 0) partial[tid >> 5] = v;
    __syncthreads();
    if (tid == 0)
        out[b] = 1.f / (1.f + expf(-(partial[0] + partial[1] + b2[0])));
}

// ---------------------------------------------------------------------------
// Launch
// ---------------------------------------------------------------------------
extern "C" void kernel_launch(void* const* d_in, const int* in_sizes, int n_in,
                              void* d_out, int out_size)
{
    (void)in_sizes; (void)n_in; (void)out_size;
    const float* x     = (const float*)d_in[0];
    const float* W_ih0 = (const float*)d_in[1];
    const float* W_hh0 = (const float*)d_in[2];
    const float* b_ih0 = (const float*)d_in[3];
    const float* b_hh0 = (const float*)d_in[4];
    const float* W_ih1 = (const float*)d_in[5];
    const float* W_hh1 = (const float*)d_in[6];
    const float* b_ih1 = (const float*)d_in[7];
    const float* b_hh1 = (const float*)d_in[8];
    const float* W1    = (const float*)d_in[9];
    const float* b1    = (const float*)d_in[10];
    const float* W2    = (const float*)d_in[11];
    const float* b2    = (const float*)d_in[12];
    float* out = (float*)d_out;

    float *gi, *hlast;
    __nv_bfloat16 *xh, *xl, *sh, *sl, *w0h, *w0l, *w1h, *w1l;
    cudaGetSymbolAddress((void**)&gi,    g_gi);
    cudaGetSymbolAddress((void**)&hlast, g_hlast);
    cudaGetSymbolAddress((void**)&xh,  g_xh);
    cudaGetSymbolAddress((void**)&xl,  g_xl);
    cudaGetSymbolAddress((void**)&sh,  g_sh);
    cudaGetSymbolAddress((void**)&sl,  g_sl);
    cudaGetSymbolAddress((void**)&w0h, g_w0h);
    cudaGetSymbolAddress((void**)&w0l, g_w0l);
    cudaGetSymbolAddress((void**)&w1h, g_w1h);
    cudaGetSymbolAddress((void**)&w1l, g_w1l);

    dim3 tgrid(MTOT / 128, G3 / 128);   // (2048, 3)

    // prepass splits
    prep_split<<<8192, 256>>>(x, xh, xl, MTOT, II, KP0);
    prep_split<<<64, 256>>>(W_ih0, w0h, w0l, G3, II, KP0);
    prep_split<<<64, 256>>>(W_ih1, w1h, w1l, G3, HH, HH);

    // layer 0
    gemm_tc2<<<tgrid, 256>>>(xh, xl, w0h, w0l, b_ih0, gi, KP0);
    gru_layer<<<BATCH / NB, NTH>>>(gi, W_hh0, b_hh0, sh, sl, nullptr, 1);
    // layer 1
    gemm_tc2<<<tgrid, 256>>>(sh, sl, w1h, w1l, b_ih1, gi, HH);
    gru_layer<<<BATCH / NB, NTH>>>(gi, W_hh1, b_hh1, nullptr, nullptr, hlast, 0);
    // head
    head_kernel<<<BATCH, 64>>>(hlast, W1, b1, W2, b2, out);
}

// round 6
// speedup vs baseline: 1.0179x; 1.0179x over previous
#include <cuda_runtime.h>
#include <cuda_bf16.h>
#include <math.h>

typedef unsigned long long ull;
typedef unsigned int uint;
typedef unsigned short ushort;

// Problem constants
#define BATCH 1024
#define TT    256
#define II    153
#define KP0   160        // II padded to multiple of 16
#define HH    128
#define G3    384
#define MTOT  (BATCH*TT)   // 262144

// ---------------------------------------------------------------------------
// Scratch (device globals — no runtime allocation allowed)
// ---------------------------------------------------------------------------
__device__ float g_gi[(size_t)MTOT * G3];                 // ~403 MB
__device__ __nv_bfloat16 g_xh[(size_t)MTOT * KP0];        // 84 MB
__device__ __nv_bfloat16 g_xl[(size_t)MTOT * KP0];        // 84 MB
__device__ __nv_bfloat16 g_sh[(size_t)MTOT * HH];         // 67 MB (seq hi)
__device__ __nv_bfloat16 g_sl[(size_t)MTOT * HH];         // 67 MB (seq lo)
__device__ __nv_bfloat16 g_w0h[G3 * KP0], g_w0l[G3 * KP0];
__device__ __nv_bfloat16 g_w1h[G3 * HH],  g_w1l[G3 * HH];
__device__ float g_hlast[BATCH * HH];

// ---------------------------------------------------------------------------
// f32x2 packed math (GRU kernel)
// ---------------------------------------------------------------------------
__device__ __forceinline__ ull pack2(float x, float y) {
    ull r; asm("mov.b64 %0, {%1, %2};" : "=l"(r) : "f"(x), "f"(y)); return r;
}
__device__ __forceinline__ void unpack2(ull v, float& x, float& y) {
    asm("mov.b64 {%0, %1}, %2;" : "=f"(x), "=f"(y) : "l"(v));
}
__device__ __forceinline__ ull fma2(ull a, ull b, ull c) {
    ull d; asm("fma.rn.f32x2 %0, %1, %2, %3;" : "=l"(d) : "l"(a), "l"(b), "l"(c));
    return d;
}

// ---------------------------------------------------------------------------
// bf16 split + tensor-core helpers
// ---------------------------------------------------------------------------
__device__ __forceinline__ void split_bf16(float a, __nv_bfloat16& h, __nv_bfloat16& l) {
    h = __float2bfloat16(a);
    l = __float2bfloat16(a - __bfloat162float(h));
}
__device__ __forceinline__ void ldsm_x4(uint& r0, uint& r1, uint& r2, uint& r3, uint addr) {
    asm volatile("ldmatrix.sync.aligned.m8n8.x4.shared.b16 {%0,%1,%2,%3}, [%4];"
        : "=r"(r0), "=r"(r1), "=r"(r2), "=r"(r3) : "r"(addr));
}
__device__ __forceinline__ void mma_bf16(float* d, const uint* a, const uint* b) {
    asm volatile("mma.sync.aligned.m16n8k16.row.col.f32.bf16.bf16.f32 "
        "{%0,%1,%2,%3}, {%4,%5,%6,%7}, {%8,%9}, {%0,%1,%2,%3};"
        : "+f"(d[0]), "+f"(d[1]), "+f"(d[2]), "+f"(d[3])
        : "r"(a[0]), "r"(a[1]), "r"(a[2]), "r"(a[3]), "r"(b[0]), "r"(b[1]));
}
__device__ __forceinline__ void cp16(uint dst, const void* src) {
    asm volatile("cp.async.cg.shared.global [%0], [%1], 16;" :: "r"(dst), "l"(src));
}
#define CP_COMMIT() asm volatile("cp.async.commit_group;")
#define CP_WAIT0()  asm volatile("cp.async.wait_group 0;")

// ---------------------------------------------------------------------------
// Prepass: split fp32 [rows,Kin] -> bf16 hi/lo [rows,Kout], zero-padded.
// Warp-per-row: NO integer divisions in the hot path, fully coalesced.
// ---------------------------------------------------------------------------
__global__ void prep_split_rows(const float* __restrict__ in,
                                __nv_bfloat16* __restrict__ oh,
                                __nv_bfloat16* __restrict__ ol,
                                int rows, int Kin, int Kout)
{
    const int warp = (blockIdx.x * blockDim.x + threadIdx.x) >> 5;
    const int lane = threadIdx.x & 31;
    if (warp >= rows) return;
    const float* src = in + (size_t)warp * Kin;
    const size_t o = (size_t)warp * Kout;
    for (int k = lane; k < Kout; k += 32) {
        float v = (k < Kin) ? src[k] : 0.f;
        __nv_bfloat16 h, l;
        split_bf16(v, h, l);
        oh[o + k] = h;
        ol[o + k] = l;
    }
}

// ---------------------------------------------------------------------------
// Pure-bf16 tensor-core GEMM, 3-term split accumulation (R5, proven):
//   C[M,384] = (Ah+Al)[M,K] @ (Bh+Bl)[384,K]^T + bias  (Al*Bl dropped)
// CTA tile 128x128, 8 warps (2m x 4n), K multiple of 16, cp.async pipeline.
// ---------------------------------------------------------------------------
#define TLD 40

__global__ __launch_bounds__(256, 2)
void gemm_tc2(const __nv_bfloat16* __restrict__ Ah, const __nv_bfloat16* __restrict__ Al,
              const __nv_bfloat16* __restrict__ Bh, const __nv_bfloat16* __restrict__ Bl,
              const float* __restrict__ bias, float* __restrict__ C, int K)
{
    __shared__ __align__(16) ushort sa[2][128 * TLD];
    __shared__ __align__(16) ushort sb[2][128 * TLD];

    const int tid  = threadIdx.x;
    const int warp = tid >> 5;
    const int lane = tid & 31;
    const size_t m0 = (size_t)blockIdx.x * 128;
    const int n0 = blockIdx.y * 128;
    const int wm = (warp >> 2) * 64;
    const int wn = (warp & 3) * 32;

    const uint sa0 = (uint)__cvta_generic_to_shared(&sa[0][0]);
    const uint sb0 = (uint)__cvta_generic_to_shared(&sb[0][0]);
    const uint bufstride = 128 * TLD * 2;

    float acc[4][4][4];
#pragma unroll
    for (int i = 0; i < 4; i++)
#pragma unroll
        for (int j = 0; j < 4; j++)
#pragma unroll
            for (int v = 0; v < 4; v++) acc[i][j][v] = 0.f;

    const int KT = K >> 4;

    const __nv_bfloat16* srcs[4];
    uint dsts[4];
    size_t srcoff[4];
#pragma unroll
    for (int i = 0; i < 4; i++) {
        int s   = tid + 256 * i;
        int mat = s >> 9;
        int r   = (s >> 2) & 127;
        int seg = s & 3;
        const __nv_bfloat16* base =
            mat ? (seg < 2 ? Bh : Bl) : (seg < 2 ? Ah : Al);
        size_t row = mat ? (size_t)(n0 + r) : (m0 + r);
        srcs[i]   = base;
        srcoff[i] = row * K + (seg & 1) * 8;
        dsts[i]   = (mat ? sb0 : sa0) + (uint)(r * 80 + seg * 16);
    }

#pragma unroll
    for (int i = 0; i < 4; i++)
        cp16(dsts[i], srcs[i] + srcoff[i]);
    CP_COMMIT();

    int buf = 0;
    for (int kt = 0; kt < KT; kt++) {
        CP_WAIT0();
        __syncthreads();

        if (kt + 1 < KT) {
            uint doff = (buf ^ 1) * bufstride;
            size_t koff = (size_t)(kt + 1) * 16;
#pragma unroll
            for (int i = 0; i < 4; i++)
                cp16(dsts[i] + doff, srcs[i] + srcoff[i] + koff);
            CP_COMMIT();
        }

        uint sa_base = sa0 + buf * bufstride;
        uint sb_base = sb0 + buf * bufstride;

        uint bhf[8], blf[8];
#pragma unroll
        for (int g = 0; g < 2; g++) {
            int nrow = wn + g * 16 + ((lane & 16) >> 1) + (lane & 7);
            int kcol = ((lane >> 3) & 1) * 8;
            ldsm_x4(bhf[g*4+0], bhf[g*4+1], bhf[g*4+2], bhf[g*4+3],
                    sb_base + (uint)(nrow * TLD + kcol) * 2u);
            ldsm_x4(blf[g*4+0], blf[g*4+1], blf[g*4+2], blf[g*4+3],
                    sb_base + (uint)(nrow * TLD + 16 + kcol) * 2u);
        }

#pragma unroll
        for (int mi = 0; mi < 4; mi++) {
            int arow = wm + mi * 16 + (lane & 15);
            int acol = ((lane >> 4) & 1) * 8;
            uint ah[4], al[4];
            ldsm_x4(ah[0], ah[1], ah[2], ah[3],
                    sa_base + (uint)(arow * TLD + acol) * 2u);
            ldsm_x4(al[0], al[1], al[2], al[3],
                    sa_base + (uint)(arow * TLD + 16 + acol) * 2u);
#pragma unroll
            for (int ni = 0; ni < 4; ni++) {
                mma_bf16(acc[mi][ni], ah, &bhf[ni*2]);
                mma_bf16(acc[mi][ni], ah, &blf[ni*2]);
                mma_bf16(acc[mi][ni], al, &bhf[ni*2]);
            }
        }
        buf ^= 1;
    }

    const int r = lane >> 2;
    const int c2 = (lane & 3) * 2;
#pragma unroll
    for (int mi = 0; mi < 4; mi++) {
#pragma unroll
        for (int ni = 0; ni < 4; ni++) {
            int n = n0 + wn + ni * 8 + c2;
            float b0 = bias[n], b1 = bias[n + 1];
            size_t m = m0 + wm + mi * 16 + r;
            float2 v0 = { acc[mi][ni][0] + b0, acc[mi][ni][1] + b1 };
            float2 v1 = { acc[mi][ni][2] + b0, acc[mi][ni][3] + b1 };
            *(float2*)&C[m * G3 + n]       = v0;
            *(float2*)&C[(m + 8) * G3 + n] = v1;
        }
    }
}

// ---------------------------------------------------------------------------
// GRU recurrence — W_hh in registers (R4, proven). Layer 0 writes seq as
// bf16 hi/lo splits directly (feeds the pure-bf16 layer-1 GEMM).
// ---------------------------------------------------------------------------
#define NB 8
#define NTH 384

__global__ __launch_bounds__(NTH)
void gru_layer(const float* __restrict__ gi,     // [B*T, 384]
               const float* __restrict__ W_hh,   // [384, 128]
               const float* __restrict__ b_hh,   // [384]
               __nv_bfloat16* __restrict__ seqh, // [B*T, 128] (layer 0)
               __nv_bfloat16* __restrict__ seql,
               float* __restrict__ hlast_out,    // [B, 128]   (layer 1)
               int write_seq)
{
    __shared__ float hs[NB][HH];
    __shared__ float rb[NB][HH];
    __shared__ float zb[NB][HH];

    const int gid = threadIdx.x;
    const int b0  = blockIdx.x * NB;
    const int j   = gid & 127;
    const int gtype = gid >> 7;

    ull Wp[64];
#pragma unroll
    for (int i = 0; i < 64; i++) {
        float2 w = *(const float2*)&W_hh[(size_t)gid * HH + 2 * i];
        Wp[i] = pack2(w.x, w.y);
    }

    for (int i = gid; i < NB * HH; i += NTH) (&hs[0][0])[i] = 0.f;
    const float bh = b_hh[gid];
    __syncthreads();

    for (int t = 0; t < TT; t++) {
        float giv[NB];
#pragma unroll
        for (int b = 0; b < NB; b++)
            giv[b] = gi[((size_t)((b0 + b) * TT + t)) * G3 + gid];

        ull acc[NB];
        const ull zz = pack2(0.f, 0.f);
#pragma unroll
        for (int b = 0; b < NB; b++) acc[b] = zz;

#pragma unroll
        for (int c = 0; c < 32; c++) {
#pragma unroll
            for (int b = 0; b < NB; b++) {
                ulonglong2 hv = *(const ulonglong2*)&hs[b][4 * c];
                acc[b] = fma2(Wp[2 * c],     hv.x, acc[b]);
                acc[b] = fma2(Wp[2 * c + 1], hv.y, acc[b]);
            }
        }

        float gh[NB];
#pragma unroll
        for (int b = 0; b < NB; b++) {
            float x, y; unpack2(acc[b], x, y);
            gh[b] = x + y + bh;
        }

        if (gtype == 0) {
#pragma unroll
            for (int b = 0; b < NB; b++)
                rb[b][j] = 1.f / (1.f + expf(-(giv[b] + gh[b])));
        } else if (gtype == 1) {
#pragma unroll
            for (int b = 0; b < NB; b++)
                zb[b][j] = 1.f / (1.f + expf(-(giv[b] + gh[b])));
        }
        __syncthreads();

        if (gtype == 2) {
#pragma unroll
            for (int b = 0; b < NB; b++) {
                float r = rb[b][j];
                float z = zb[b][j];
                float n = tanhf(giv[b] + r * gh[b]);
                float hn = (1.f - z) * n + z * hs[b][j];
                hs[b][j] = hn;
                if (write_seq) {
                    __nv_bfloat16 hh, hl;
                    split_bf16(hn, hh, hl);
                    size_t m = (size_t)((b0 + b) * TT + t) * HH + j;
                    seqh[m] = hh;
                    seql[m] = hl;
                }
            }
        }
        __syncthreads();
    }

    if (!write_seq && gtype == 2) {
#pragma unroll
        for (int b = 0; b < NB; b++)
            hlast_out[(b0 + b) * HH + j] = hs[b][j];
    }
}

// ---------------------------------------------------------------------------
// head — Linear(128,64) -> ReLU -> Linear(64,1) -> Sigmoid
// ---------------------------------------------------------------------------
__global__ __launch_bounds__(64)
void head_kernel(const float* __restrict__ hlast, const float* __restrict__ W1,
                 const float* __restrict__ b1, const float* __restrict__ W2,
                 const float* __restrict__ b2, float* __restrict__ out)
{
    __shared__ float hsm[HH];
    __shared__ float partial[2];
    const int b = blockIdx.x, tid = threadIdx.x;

    hsm[tid]      = hlast[b * HH + tid];
    hsm[tid + 64] = hlast[b * HH + 64 + tid];
    __syncthreads();

    float acc = b1[tid];
#pragma unroll 4
    for (int k = 0; k < HH; k++)
        acc += hsm[k] * W1[tid * HH + k];
    float v = fmaxf(acc, 0.f) * W2[tid];

#pragma unroll
    for (int o = 16; o > 0; o >>= 1)
        v += __shfl_down_sync(0xffffffffu, v, o);
    if ((tid & 31) == 0) partial[tid >> 5] = v;
    __syncthreads();
    if (tid == 0)
        out[b] = 1.f / (1.f + expf(-(partial[0] + partial[1] + b2[0])));
}

// ---------------------------------------------------------------------------
// Launch
// ---------------------------------------------------------------------------
extern "C" void kernel_launch(void* const* d_in, const int* in_sizes, int n_in,
                              void* d_out, int out_size)
{
    (void)in_sizes; (void)n_in; (void)out_size;
    const float* x     = (const float*)d_in[0];
    const float* W_ih0 = (const float*)d_in[1];
    const float* W_hh0 = (const float*)d_in[2];
    const float* b_ih0 = (const float*)d_in[3];
    const float* b_hh0 = (const float*)d_in[4];
    const float* W_ih1 = (const float*)d_in[5];
    const float* W_hh1 = (const float*)d_in[6];
    const float* b_ih1 = (const float*)d_in[7];
    const float* b_hh1 = (const float*)d_in[8];
    const float* W1    = (const float*)d_in[9];
    const float* b1    = (const float*)d_in[10];
    const float* W2    = (const float*)d_in[11];
    const float* b2    = (const float*)d_in[12];
    float* out = (float*)d_out;

    float *gi, *hlast;
    __nv_bfloat16 *xh, *xl, *sh, *sl, *w0h, *w0l, *w1h, *w1l;
    cudaGetSymbolAddress((void**)&gi,    g_gi);
    cudaGetSymbolAddress((void**)&hlast, g_hlast);
    cudaGetSymbolAddress((void**)&xh,  g_xh);
    cudaGetSymbolAddress((void**)&xl,  g_xl);
    cudaGetSymbolAddress((void**)&sh,  g_sh);
    cudaGetSymbolAddress((void**)&sl,  g_sl);
    cudaGetSymbolAddress((void**)&w0h, g_w0h);
    cudaGetSymbolAddress((void**)&w0l, g_w0l);
    cudaGetSymbolAddress((void**)&w1h, g_w1h);
    cudaGetSymbolAddress((void**)&w1l, g_w1l);

    dim3 tgrid(MTOT / 128, G3 / 128);   // (2048, 3)

    // prepass splits (warp-per-row, division-free)
    prep_split_rows<<<MTOT / 8, 256>>>(x, xh, xl, MTOT, II, KP0);
    prep_split_rows<<<G3 / 8, 256>>>(W_ih0, w0h, w0l, G3, II, KP0);
    prep_split_rows<<<G3 / 8, 256>>>(W_ih1, w1h, w1l, G3, HH, HH);

    // layer 0
    gemm_tc2<<<tgrid, 256>>>(xh, xl, w0h, w0l, b_ih0, gi, KP0);
    gru_layer<<<BATCH / NB, NTH>>>(gi, W_hh0, b_hh0, sh, sl, nullptr, 1);
    // layer 1
    gemm_tc2<<<tgrid, 256>>>(sh, sl, w1h, w1l, b_ih1, gi, HH);
    gru_layer<<<BATCH / NB, NTH>>>(gi, W_hh1, b_hh1, nullptr, nullptr, hlast, 0);
    // head
    head_kernel<<<BATCH, 64>>>(hlast, W1, b1, W2, b2, out);
}

// round 7
// speedup vs baseline: 1.2865x; 1.2639x over previous
#include <cuda_runtime.h>
#include <cuda_bf16.h>
#include <math.h>

typedef unsigned long long ull;
typedef unsigned int uint;
typedef unsigned short ushort;

// Problem constants
#define BATCH 1024
#define TT    256
#define II    153
#define KP0   160        // II padded to multiple of 16
#define HH    128
#define G3    384
#define MTOT  (BATCH*TT)   // 262144

// ---------------------------------------------------------------------------
// Scratch (device globals — no runtime allocation allowed)
// ---------------------------------------------------------------------------
__device__ float g_gi[(size_t)MTOT * G3];                 // ~403 MB
__device__ __nv_bfloat16 g_xh[(size_t)MTOT * KP0];
__device__ __nv_bfloat16 g_xl[(size_t)MTOT * KP0];
__device__ __nv_bfloat16 g_sh[(size_t)MTOT * HH];
__device__ __nv_bfloat16 g_sl[(size_t)MTOT * HH];
__device__ __nv_bfloat16 g_w0h[G3 * KP0], g_w0l[G3 * KP0];
__device__ __nv_bfloat16 g_w1h[G3 * HH],  g_w1l[G3 * HH];
__device__ float g_hlast[BATCH * HH];

// ---------------------------------------------------------------------------
// bf16 split + tensor-core helpers
// ---------------------------------------------------------------------------
__device__ __forceinline__ void split_bf16(float a, __nv_bfloat16& h, __nv_bfloat16& l) {
    h = __float2bfloat16(a);
    l = __float2bfloat16(a - __bfloat162float(h));
}
__device__ __forceinline__ void ldsm_x4(uint& r0, uint& r1, uint& r2, uint& r3, uint addr) {
    asm volatile("ldmatrix.sync.aligned.m8n8.x4.shared.b16 {%0,%1,%2,%3}, [%4];"
        : "=r"(r0), "=r"(r1), "=r"(r2), "=r"(r3) : "r"(addr));
}
__device__ __forceinline__ void mma_bf16(float* d, const uint* a, const uint* b) {
    asm volatile("mma.sync.aligned.m16n8k16.row.col.f32.bf16.bf16.f32 "
        "{%0,%1,%2,%3}, {%4,%5,%6,%7}, {%8,%9}, {%0,%1,%2,%3};"
        : "+f"(d[0]), "+f"(d[1]), "+f"(d[2]), "+f"(d[3])
        : "r"(a[0]), "r"(a[1]), "r"(a[2]), "r"(a[3]), "r"(b[0]), "r"(b[1]));
}
__device__ __forceinline__ void cp16(uint dst, const void* src) {
    asm volatile("cp.async.cg.shared.global [%0], [%1], 16;" :: "r"(dst), "l"(src));
}
#define CP_COMMIT() asm volatile("cp.async.commit_group;")
#define CP_WAIT0()  asm volatile("cp.async.wait_group 0;")

// ---------------------------------------------------------------------------
// Prepass: split fp32 [rows,Kin] -> bf16 hi/lo [rows,Kout], zero-padded.
// ---------------------------------------------------------------------------
__global__ void prep_split_rows(const float* __restrict__ in,
                                __nv_bfloat16* __restrict__ oh,
                                __nv_bfloat16* __restrict__ ol,
                                int rows, int Kin, int Kout)
{
    const int warp = (blockIdx.x * blockDim.x + threadIdx.x) >> 5;
    const int lane = threadIdx.x & 31;
    if (warp >= rows) return;
    const float* src = in + (size_t)warp * Kin;
    const size_t o = (size_t)warp * Kout;
    for (int k = lane; k < Kout; k += 32) {
        float v = (k < Kin) ? src[k] : 0.f;
        __nv_bfloat16 h, l;
        split_bf16(v, h, l);
        oh[o + k] = h;
        ol[o + k] = l;
    }
}

// ---------------------------------------------------------------------------
// Pure-bf16 tensor-core GEMM (R5, proven)
// ---------------------------------------------------------------------------
#define TLD 40

__global__ __launch_bounds__(256, 2)
void gemm_tc2(const __nv_bfloat16* __restrict__ Ah, const __nv_bfloat16* __restrict__ Al,
              const __nv_bfloat16* __restrict__ Bh, const __nv_bfloat16* __restrict__ Bl,
              const float* __restrict__ bias, float* __restrict__ C, int K)
{
    __shared__ __align__(16) ushort sa[2][128 * TLD];
    __shared__ __align__(16) ushort sb[2][128 * TLD];

    const int tid  = threadIdx.x;
    const int warp = tid >> 5;
    const int lane = tid & 31;
    const size_t m0 = (size_t)blockIdx.x * 128;
    const int n0 = blockIdx.y * 128;
    const int wm = (warp >> 2) * 64;
    const int wn = (warp & 3) * 32;

    const uint sa0 = (uint)__cvta_generic_to_shared(&sa[0][0]);
    const uint sb0 = (uint)__cvta_generic_to_shared(&sb[0][0]);
    const uint bufstride = 128 * TLD * 2;

    float acc[4][4][4];
#pragma unroll
    for (int i = 0; i < 4; i++)
#pragma unroll
        for (int j = 0; j < 4; j++)
#pragma unroll
            for (int v = 0; v < 4; v++) acc[i][j][v] = 0.f;

    const int KT = K >> 4;

    const __nv_bfloat16* srcs[4];
    uint dsts[4];
    size_t srcoff[4];
#pragma unroll
    for (int i = 0; i < 4; i++) {
        int s   = tid + 256 * i;
        int mat = s >> 9;
        int r   = (s >> 2) & 127;
        int seg = s & 3;
        const __nv_bfloat16* base =
            mat ? (seg < 2 ? Bh : Bl) : (seg < 2 ? Ah : Al);
        size_t row = mat ? (size_t)(n0 + r) : (m0 + r);
        srcs[i]   = base;
        srcoff[i] = row * K + (seg & 1) * 8;
        dsts[i]   = (mat ? sb0 : sa0) + (uint)(r * 80 + seg * 16);
    }

#pragma unroll
    for (int i = 0; i < 4; i++)
        cp16(dsts[i], srcs[i] + srcoff[i]);
    CP_COMMIT();

    int buf = 0;
    for (int kt = 0; kt < KT; kt++) {
        CP_WAIT0();
        __syncthreads();

        if (kt + 1 < KT) {
            uint doff = (buf ^ 1) * bufstride;
            size_t koff = (size_t)(kt + 1) * 16;
#pragma unroll
            for (int i = 0; i < 4; i++)
                cp16(dsts[i] + doff, srcs[i] + srcoff[i] + koff);
            CP_COMMIT();
        }

        uint sa_base = sa0 + buf * bufstride;
        uint sb_base = sb0 + buf * bufstride;

        uint bhf[8], blf[8];
#pragma unroll
        for (int g = 0; g < 2; g++) {
            int nrow = wn + g * 16 + ((lane & 16) >> 1) + (lane & 7);
            int kcol = ((lane >> 3) & 1) * 8;
            ldsm_x4(bhf[g*4+0], bhf[g*4+1], bhf[g*4+2], bhf[g*4+3],
                    sb_base + (uint)(nrow * TLD + kcol) * 2u);
            ldsm_x4(blf[g*4+0], blf[g*4+1], blf[g*4+2], blf[g*4+3],
                    sb_base + (uint)(nrow * TLD + 16 + kcol) * 2u);
        }

#pragma unroll
        for (int mi = 0; mi < 4; mi++) {
            int arow = wm + mi * 16 + (lane & 15);
            int acol = ((lane >> 4) & 1) * 8;
            uint ah[4], al[4];
            ldsm_x4(ah[0], ah[1], ah[2], ah[3],
                    sa_base + (uint)(arow * TLD + acol) * 2u);
            ldsm_x4(al[0], al[1], al[2], al[3],
                    sa_base + (uint)(arow * TLD + 16 + acol) * 2u);
#pragma unroll
            for (int ni = 0; ni < 4; ni++) {
                mma_bf16(acc[mi][ni], ah, &bhf[ni*2]);
                mma_bf16(acc[mi][ni], ah, &blf[ni*2]);
                mma_bf16(acc[mi][ni], al, &bhf[ni*2]);
            }
        }
        buf ^= 1;
    }

    const int r = lane >> 2;
    const int c2 = (lane & 3) * 2;
#pragma unroll
    for (int mi = 0; mi < 4; mi++) {
#pragma unroll
        for (int ni = 0; ni < 4; ni++) {
            int n = n0 + wn + ni * 8 + c2;
            float b0 = bias[n], b1 = bias[n + 1];
            size_t m = m0 + wm + mi * 16 + r;
            float2 v0 = { acc[mi][ni][0] + b0, acc[mi][ni][1] + b1 };
            float2 v1 = { acc[mi][ni][2] + b0, acc[mi][ni][3] + b1 };
            *(float2*)&C[m * G3 + n]       = v0;
            *(float2*)&C[(m + 8) * G3 + n] = v1;
        }
    }
}

// ---------------------------------------------------------------------------
// GRU recurrence on TENSOR CORES.
// One CTA = 8 batch rows, 384 threads = 12 warps; warp w owns gates
// [32w, 32w+32). Per step: gh[8,384] = h[8,128] @ W_hh^T via bf16
// mma.m16n8k16 with 3-term hi/lo split (hh*Wh + hh*Wl + hl*Wh).
// W_hh hi/lo bf16 in smem, XOR-swizzled rows (256B/row, seg ^= row&7).
// h A-tiles (16x128, rows 8-15 zero) re-split to bf16 each step.
// D rows 0-7 -> sgh (per-warp column slice) -> gate phase in SAME warp.
// ---------------------------------------------------------------------------
#define NB 8
#define GNTH 384
// smem byte offsets
#define SWH_OFF 0
#define SWL_OFF 98304
#define SAH_OFF 196608
#define SAL_OFF 200704
#define HS_OFF  204800
#define SGH_OFF 208896
#define RB_OFF  221504
#define ZB_OFF  225600
#define GRU_SMEM 229696
#define SGH_P   394      // sgh row pitch in floats (b*394*4B: banks 10*b mod 32, all distinct)

__global__ __launch_bounds__(GNTH)
void gru_layer_tc(const float* __restrict__ gi,     // [B*T, 384]
                  const float* __restrict__ W_hh,   // [384, 128]
                  const float* __restrict__ b_hh,   // [384]
                  __nv_bfloat16* __restrict__ seqh, // [B*T, 128] (layer 0)
                  __nv_bfloat16* __restrict__ seql,
                  float* __restrict__ hlast_out,    // [B, 128]   (layer 1)
                  int write_seq)
{
    extern __shared__ char sm[];
    float* hs  = (float*)(sm + HS_OFF);    // [8][128]
    float* sgh = (float*)(sm + SGH_OFF);   // [8][SGH_P]
    float* rb  = (float*)(sm + RB_OFF);    // [8][128]
    float* zb  = (float*)(sm + ZB_OFF);    // [8][128]
    const uint sbase = (uint)__cvta_generic_to_shared(sm);

    const int tid  = threadIdx.x;           // == gate id 0..383
    const int lane = tid & 31;
    const int warp = tid >> 5;
    const int G0   = warp * 32;
    const int b0   = blockIdx.x * NB;
    const int j    = tid & 127;
    const int gtype = tid >> 7;              // 0=r warps0-3, 1=z warps4-7, 2=n warps8-11

    // ---- init: W_hh -> swizzled bf16 hi/lo in smem (gate-major, 256B rows)
    {
        const int gsw = tid & 7;
#pragma unroll 4
        for (int k = 0; k < HH; k++) {
            float w = W_hh[(size_t)tid * HH + k];
            __nv_bfloat16 h, l;
            split_bf16(w, h, l);
            int off = tid * 256 + (((k >> 3) ^ gsw) << 4) + (k & 7) * 2;
            *(__nv_bfloat16*)(sm + SWH_OFF + off) = h;
            *(__nv_bfloat16*)(sm + SWL_OFF + off) = l;
        }
    }
    // zero A tiles (8KB: sAh+sAl contiguous) and hs
    for (int i = tid; i < 2048; i += GNTH) ((uint*)(sm + SAH_OFF))[i] = 0;
    for (int i = tid; i < 1024; i += GNTH) ((uint*)(sm + HS_OFF))[i] = 0;
    const float bh = b_hh[tid];
    __syncthreads();

    // precomputed ldmatrix addresses (step-invariant except kt)
    const uint arow = lane & 15;
    const uint abase = arow * 256u;
    const uint asw = arow & 7;
    const uint aseg0 = (uint)(lane >> 4);           // 0 or 1
    const uint wrow = (uint)(G0 + ((lane & 16) >> 1) + (lane & 7));  // gg=0 row
    const uint wseg0 = (uint)((lane >> 3) & 1);

    for (int t = 0; t < TT; t++) {
        // prefetch gi (DRAM latency hidden behind the mma phase)
        float giv[NB];
#pragma unroll
        for (int b = 0; b < NB; b++)
            giv[b] = gi[((size_t)((b0 + b) * TT + t)) * G3 + tid];

        float acc[4][4];
#pragma unroll
        for (int ni = 0; ni < 4; ni++)
#pragma unroll
            for (int v = 0; v < 4; v++) acc[ni][v] = 0.f;

#pragma unroll
        for (int kt = 0; kt < 8; kt++) {
            uint aoff = abase + ((((uint)(kt * 2) + aseg0) ^ asw) << 4);
            uint ah[4], al[4];
            ldsm_x4(ah[0], ah[1], ah[2], ah[3], sbase + SAH_OFF + aoff);
            ldsm_x4(al[0], al[1], al[2], al[3], sbase + SAL_OFF + aoff);

            uint wh[8], wl[8];
#pragma unroll
            for (int gg = 0; gg < 2; gg++) {
                uint row = wrow + gg * 16;
                uint seg = (uint)(kt * 2) + wseg0;
                uint woff = row * 256u + (((seg ^ (row & 7)) ) << 4);
                ldsm_x4(wh[gg*4+0], wh[gg*4+1], wh[gg*4+2], wh[gg*4+3],
                        sbase + SWH_OFF + woff);
                ldsm_x4(wl[gg*4+0], wl[gg*4+1], wl[gg*4+2], wl[gg*4+3],
                        sbase + SWL_OFF + woff);
            }
#pragma unroll
            for (int ni = 0; ni < 4; ni++) {
                mma_bf16(acc[ni], ah, &wh[ni*2]);
                mma_bf16(acc[ni], ah, &wl[ni*2]);
                mma_bf16(acc[ni], al, &wh[ni*2]);
            }
        }

        // D rows 0-7 (real batches) -> sgh[b][G0..G0+31]
        {
            const int brow = lane >> 2;           // 0..7 = batch
            const int c = (lane & 3) * 2;
            float* p = sgh + brow * SGH_P + G0;
#pragma unroll
            for (int ni = 0; ni < 4; ni++) {
                float2 v = { acc[ni][0], acc[ni][1] };
                *(float2*)(p + ni * 8 + c) = v;
            }
        }
        __syncwarp();

        // gate phase: thread = gate tid (its gh was computed by its own warp)
        float ghv[NB];
#pragma unroll
        for (int b = 0; b < NB; b++)
            ghv[b] = sgh[b * SGH_P + tid] + bh;

        if (gtype == 0) {
#pragma unroll
            for (int b = 0; b < NB; b++)
                rb[b * HH + j] = 1.f / (1.f + expf(-(giv[b] + ghv[b])));
        } else if (gtype == 1) {
#pragma unroll
            for (int b = 0; b < NB; b++)
                zb[b * HH + j] = 1.f / (1.f + expf(-(giv[b] + ghv[b])));
        }
        __syncthreads();

        if (gtype == 2) {
            const int jsw = j & 7;
            const int seg = j >> 3;
#pragma unroll
            for (int b = 0; b < NB; b++) {
                float r = rb[b * HH + j];
                float z = zb[b * HH + j];
                float n = tanhf(giv[b] + r * ghv[b]);
                float hn = (1.f - z) * n + z * hs[b * HH + j];
                hs[b * HH + j] = hn;
                __nv_bfloat16 hh, hl;
                split_bf16(hn, hh, hl);
                int aoff = b * 256 + ((seg ^ (b & 7)) << 4) + jsw * 2;
                *(__nv_bfloat16*)(sm + SAH_OFF + aoff) = hh;
                *(__nv_bfloat16*)(sm + SAL_OFF + aoff) = hl;
                if (write_seq) {
                    size_t m = (size_t)((b0 + b) * TT + t) * HH + j;
                    seqh[m] = hh;
                    seql[m] = hl;
                }
            }
        }
        __syncthreads();
    }

    if (!write_seq && gtype == 2) {
#pragma unroll
        for (int b = 0; b < NB; b++)
            hlast_out[(b0 + b) * HH + j] = hs[b * HH + j];
    }
}

// ---------------------------------------------------------------------------
// head — Linear(128,64) -> ReLU -> Linear(64,1) -> Sigmoid
// ---------------------------------------------------------------------------
__global__ __launch_bounds__(64)
void head_kernel(const float* __restrict__ hlast, const float* __restrict__ W1,
                 const float* __restrict__ b1, const float* __restrict__ W2,
                 const float* __restrict__ b2, float* __restrict__ out)
{
    __shared__ float hsm[HH];
    __shared__ float partial[2];
    const int b = blockIdx.x, tid = threadIdx.x;

    hsm[tid]      = hlast[b * HH + tid];
    hsm[tid + 64] = hlast[b * HH + 64 + tid];
    __syncthreads();

    float acc = b1[tid];
#pragma unroll 4
    for (int k = 0; k < HH; k++)
        acc += hsm[k] * W1[tid * HH + k];
    float v = fmaxf(acc, 0.f) * W2[tid];

#pragma unroll
    for (int o = 16; o > 0; o >>= 1)
        v += __shfl_down_sync(0xffffffffu, v, o);
    if ((tid & 31) == 0) partial[tid >> 5] = v;
    __syncthreads();
    if (tid == 0)
        out[b] = 1.f / (1.f + expf(-(partial[0] + partial[1] + b2[0])));
}

// ---------------------------------------------------------------------------
// Launch
// ---------------------------------------------------------------------------
extern "C" void kernel_launch(void* const* d_in, const int* in_sizes, int n_in,
                              void* d_out, int out_size)
{
    (void)in_sizes; (void)n_in; (void)out_size;
    const float* x     = (const float*)d_in[0];
    const float* W_ih0 = (const float*)d_in[1];
    const float* W_hh0 = (const float*)d_in[2];
    const float* b_ih0 = (const float*)d_in[3];
    const float* b_hh0 = (const float*)d_in[4];
    const float* W_ih1 = (const float*)d_in[5];
    const float* W_hh1 = (const float*)d_in[6];
    const float* b_ih1 = (const float*)d_in[7];
    const float* b_hh1 = (const float*)d_in[8];
    const float* W1    = (const float*)d_in[9];
    const float* b1    = (const float*)d_in[10];
    const float* W2    = (const float*)d_in[11];
    const float* b2    = (const float*)d_in[12];
    float* out = (float*)d_out;

    float *gi, *hlast;
    __nv_bfloat16 *xh, *xl, *sh, *sl, *w0h, *w0l, *w1h, *w1l;
    cudaGetSymbolAddress((void**)&gi,    g_gi);
    cudaGetSymbolAddress((void**)&hlast, g_hlast);
    cudaGetSymbolAddress((void**)&xh,  g_xh);
    cudaGetSymbolAddress((void**)&xl,  g_xl);
    cudaGetSymbolAddress((void**)&sh,  g_sh);
    cudaGetSymbolAddress((void**)&sl,  g_sl);
    cudaGetSymbolAddress((void**)&w0h, g_w0h);
    cudaGetSymbolAddress((void**)&w0l, g_w0l);
    cudaGetSymbolAddress((void**)&w1h, g_w1h);
    cudaGetSymbolAddress((void**)&w1l, g_w1l);

    cudaFuncSetAttribute(gru_layer_tc, cudaFuncAttributeMaxDynamicSharedMemorySize,
                         GRU_SMEM);

    dim3 tgrid(MTOT / 128, G3 / 128);   // (2048, 3)

    // prepass splits (warp-per-row, division-free)
    prep_split_rows<<<MTOT / 8, 256>>>(x, xh, xl, MTOT, II, KP0);
    prep_split_rows<<<G3 / 8, 256>>>(W_ih0, w0h, w0l, G3, II, KP0);
    prep_split_rows<<<G3 / 8, 256>>>(W_ih1, w1h, w1l, G3, HH, HH);

    // layer 0
    gemm_tc2<<<tgrid, 256>>>(xh, xl, w0h, w0l, b_ih0, gi, KP0);
    gru_layer_tc<<<BATCH / NB, GNTH, GRU_SMEM>>>(gi, W_hh0, b_hh0, sh, sl, nullptr, 1);
    // layer 1
    gemm_tc2<<<tgrid, 256>>>(sh, sl, w1h, w1l, b_ih1, gi, HH);
    gru_layer_tc<<<BATCH / NB, GNTH, GRU_SMEM>>>(gi, W_hh1, b_hh1, nullptr, nullptr, hlast, 0);
    // head
    head_kernel<<<BATCH, 64>>>(hlast, W1, b1, W2, b2, out);
}

// round 8
// speedup vs baseline: 1.5647x; 1.2162x over previous
#include <cuda_runtime.h>
#include <cuda_bf16.h>
#include <math.h>

typedef unsigned long long ull;
typedef unsigned int uint;
typedef unsigned short ushort;

// Problem constants
#define BATCH 1024
#define TT    256
#define II    153
#define KP0   160        // II padded to multiple of 16
#define HH    128
#define G3    384
#define MTOT  (BATCH*TT)   // 262144

// ---------------------------------------------------------------------------
// Scratch (device globals — no runtime allocation allowed)
// ---------------------------------------------------------------------------
__device__ float g_gi[(size_t)MTOT * G3];                 // ~403 MB
__device__ __nv_bfloat16 g_xh[(size_t)MTOT * KP0];
__device__ __nv_bfloat16 g_xl[(size_t)MTOT * KP0];
__device__ __nv_bfloat16 g_sh[(size_t)MTOT * HH];
__device__ __nv_bfloat16 g_sl[(size_t)MTOT * HH];
__device__ __nv_bfloat16 g_w0h[G3 * KP0], g_w0l[G3 * KP0];
__device__ __nv_bfloat16 g_w1h[G3 * HH],  g_w1l[G3 * HH];
__device__ float g_hlast[BATCH * HH];

// ---------------------------------------------------------------------------
// bf16 split + tensor-core helpers
// ---------------------------------------------------------------------------
__device__ __forceinline__ void split_bf16(float a, __nv_bfloat16& h, __nv_bfloat16& l) {
    h = __float2bfloat16(a);
    l = __float2bfloat16(a - __bfloat162float(h));
}
__device__ __forceinline__ void ldsm_x4(uint& r0, uint& r1, uint& r2, uint& r3, uint addr) {
    asm volatile("ldmatrix.sync.aligned.m8n8.x4.shared.b16 {%0,%1,%2,%3}, [%4];"
        : "=r"(r0), "=r"(r1), "=r"(r2), "=r"(r3) : "r"(addr));
}
__device__ __forceinline__ void mma_bf16(float* d, const uint* a, const uint* b) {
    asm volatile("mma.sync.aligned.m16n8k16.row.col.f32.bf16.bf16.f32 "
        "{%0,%1,%2,%3}, {%4,%5,%6,%7}, {%8,%9}, {%0,%1,%2,%3};"
        : "+f"(d[0]), "+f"(d[1]), "+f"(d[2]), "+f"(d[3])
        : "r"(a[0]), "r"(a[1]), "r"(a[2]), "r"(a[3]), "r"(b[0]), "r"(b[1]));
}
__device__ __forceinline__ void cp16(uint dst, const void* src) {
    asm volatile("cp.async.cg.shared.global [%0], [%1], 16;" :: "r"(dst), "l"(src));
}
#define CP_COMMIT() asm volatile("cp.async.commit_group;")
#define CP_WAIT0()  asm volatile("cp.async.wait_group 0;")

// ---------------------------------------------------------------------------
// Prepass: split fp32 [rows,Kin] -> bf16 hi/lo [rows,Kout], zero-padded.
// ---------------------------------------------------------------------------
__global__ void prep_split_rows(const float* __restrict__ in,
                                __nv_bfloat16* __restrict__ oh,
                                __nv_bfloat16* __restrict__ ol,
                                int rows, int Kin, int Kout)
{
    const int warp = (blockIdx.x * blockDim.x + threadIdx.x) >> 5;
    const int lane = threadIdx.x & 31;
    if (warp >= rows) return;
    const float* src = in + (size_t)warp * Kin;
    const size_t o = (size_t)warp * Kout;
    for (int k = lane; k < Kout; k += 32) {
        float v = (k < Kin) ? src[k] : 0.f;
        __nv_bfloat16 h, l;
        split_bf16(v, h, l);
        oh[o + k] = h;
        ol[o + k] = l;
    }
}

// ---------------------------------------------------------------------------
// Pure-bf16 tensor-core GEMM (R5, proven)
// ---------------------------------------------------------------------------
#define TLD 40

__global__ __launch_bounds__(256, 2)
void gemm_tc2(const __nv_bfloat16* __restrict__ Ah, const __nv_bfloat16* __restrict__ Al,
              const __nv_bfloat16* __restrict__ Bh, const __nv_bfloat16* __restrict__ Bl,
              const float* __restrict__ bias, float* __restrict__ C, int K)
{
    __shared__ __align__(16) ushort sa[2][128 * TLD];
    __shared__ __align__(16) ushort sb[2][128 * TLD];

    const int tid  = threadIdx.x;
    const int warp = tid >> 5;
    const int lane = tid & 31;
    const size_t m0 = (size_t)blockIdx.x * 128;
    const int n0 = blockIdx.y * 128;
    const int wm = (warp >> 2) * 64;
    const int wn = (warp & 3) * 32;

    const uint sa0 = (uint)__cvta_generic_to_shared(&sa[0][0]);
    const uint sb0 = (uint)__cvta_generic_to_shared(&sb[0][0]);
    const uint bufstride = 128 * TLD * 2;

    float acc[4][4][4];
#pragma unroll
    for (int i = 0; i < 4; i++)
#pragma unroll
        for (int j = 0; j < 4; j++)
#pragma unroll
            for (int v = 0; v < 4; v++) acc[i][j][v] = 0.f;

    const int KT = K >> 4;

    const __nv_bfloat16* srcs[4];
    uint dsts[4];
    size_t srcoff[4];
#pragma unroll
    for (int i = 0; i < 4; i++) {
        int s   = tid + 256 * i;
        int mat = s >> 9;
        int r   = (s >> 2) & 127;
        int seg = s & 3;
        const __nv_bfloat16* base =
            mat ? (seg < 2 ? Bh : Bl) : (seg < 2 ? Ah : Al);
        size_t row = mat ? (size_t)(n0 + r) : (m0 + r);
        srcs[i]   = base;
        srcoff[i] = row * K + (seg & 1) * 8;
        dsts[i]   = (mat ? sb0 : sa0) + (uint)(r * 80 + seg * 16);
    }

#pragma unroll
    for (int i = 0; i < 4; i++)
        cp16(dsts[i], srcs[i] + srcoff[i]);
    CP_COMMIT();

    int buf = 0;
    for (int kt = 0; kt < KT; kt++) {
        CP_WAIT0();
        __syncthreads();

        if (kt + 1 < KT) {
            uint doff = (buf ^ 1) * bufstride;
            size_t koff = (size_t)(kt + 1) * 16;
#pragma unroll
            for (int i = 0; i < 4; i++)
                cp16(dsts[i] + doff, srcs[i] + srcoff[i] + koff);
            CP_COMMIT();
        }

        uint sa_base = sa0 + buf * bufstride;
        uint sb_base = sb0 + buf * bufstride;

        uint bhf[8], blf[8];
#pragma unroll
        for (int g = 0; g < 2; g++) {
            int nrow = wn + g * 16 + ((lane & 16) >> 1) + (lane & 7);
            int kcol = ((lane >> 3) & 1) * 8;
            ldsm_x4(bhf[g*4+0], bhf[g*4+1], bhf[g*4+2], bhf[g*4+3],
                    sb_base + (uint)(nrow * TLD + kcol) * 2u);
            ldsm_x4(blf[g*4+0], blf[g*4+1], blf[g*4+2], blf[g*4+3],
                    sb_base + (uint)(nrow * TLD + 16 + kcol) * 2u);
        }

#pragma unroll
        for (int mi = 0; mi < 4; mi++) {
            int arow = wm + mi * 16 + (lane & 15);
            int acol = ((lane >> 4) & 1) * 8;
            uint ah[4], al[4];
            ldsm_x4(ah[0], ah[1], ah[2], ah[3],
                    sa_base + (uint)(arow * TLD + acol) * 2u);
            ldsm_x4(al[0], al[1], al[2], al[3],
                    sa_base + (uint)(arow * TLD + 16 + acol) * 2u);
#pragma unroll
            for (int ni = 0; ni < 4; ni++) {
                mma_bf16(acc[mi][ni], ah, &bhf[ni*2]);
                mma_bf16(acc[mi][ni], ah, &blf[ni*2]);
                mma_bf16(acc[mi][ni], al, &bhf[ni*2]);
            }
        }
        buf ^= 1;
    }

    const int r = lane >> 2;
    const int c2 = (lane & 3) * 2;
#pragma unroll
    for (int mi = 0; mi < 4; mi++) {
#pragma unroll
        for (int ni = 0; ni < 4; ni++) {
            int n = n0 + wn + ni * 8 + c2;
            float b0 = bias[n], b1 = bias[n + 1];
            size_t m = m0 + wm + mi * 16 + r;
            float2 v0 = { acc[mi][ni][0] + b0, acc[mi][ni][1] + b1 };
            float2 v1 = { acc[mi][ni][2] + b0, acc[mi][ni][3] + b1 };
            *(float2*)&C[m * G3 + n]       = v0;
            *(float2*)&C[(m + 8) * G3 + n] = v1;
        }
    }
}

// ---------------------------------------------------------------------------
// GRU recurrence on tensor cores, v2:
//  * merged A-tile: rows 0-7 = h_hi, rows 8-15 = h_lo (bf16). One mma against
//    Wh/Wl produces hh*W in D rows 0-7 and hl*W in rows 8-15; gh = sum of the
//    two row-halves, done in registers (acc[0]+acc[2]). Exact 4-term product.
//  * Wh fragments in REGISTERS (loaded once via ldsm before the time loop);
//    Wl stays in smem (2 ldsm.x4/kt).
// Per warp per step: 24 ldsm.x4 + 64 mma (was 48 + 96).
// ---------------------------------------------------------------------------
#define NB 8
#define GNTH 384
// smem byte offsets
#define SWH_OFF 0
#define SWL_OFF 98304
#define SA_OFF  196608   // 16 rows x 256B (rows 0-7 hi, 8-15 lo)
#define HS_OFF  200704   // 8x128 fp32
#define SGH_OFF 204800   // 8 x SGH_P fp32
#define RB_OFF  217408
#define ZB_OFF  221504
#define GRU_SMEM 225600
#define SGH_P   394      // sgh row pitch in floats

__global__ __launch_bounds__(GNTH)
void gru_layer_tc(const float* __restrict__ gi,     // [B*T, 384]
                  const float* __restrict__ W_hh,   // [384, 128]
                  const float* __restrict__ b_hh,   // [384]
                  __nv_bfloat16* __restrict__ seqh, // [B*T, 128] (layer 0)
                  __nv_bfloat16* __restrict__ seql,
                  float* __restrict__ hlast_out,    // [B, 128]   (layer 1)
                  int write_seq)
{
    extern __shared__ char sm[];
    float* hs  = (float*)(sm + HS_OFF);
    float* sgh = (float*)(sm + SGH_OFF);
    float* rb  = (float*)(sm + RB_OFF);
    float* zb  = (float*)(sm + ZB_OFF);
    const uint sbase = (uint)__cvta_generic_to_shared(sm);

    const int tid  = threadIdx.x;           // == gate id 0..383
    const int lane = tid & 31;
    const int warp = tid >> 5;
    const int G0   = warp * 32;
    const int b0   = blockIdx.x * NB;
    const int j    = tid & 127;
    const int gtype = tid >> 7;              // 0=r, 1=z, 2=n

    // ---- init: W_hh -> swizzled bf16 hi/lo in smem (gate-major, 256B rows)
    {
        const int gsw = tid & 7;
#pragma unroll 4
        for (int k = 0; k < HH; k++) {
            float w = W_hh[(size_t)tid * HH + k];
            __nv_bfloat16 h, l;
            split_bf16(w, h, l);
            int off = tid * 256 + (((k >> 3) ^ gsw) << 4) + (k & 7) * 2;
            *(__nv_bfloat16*)(sm + SWH_OFF + off) = h;
            *(__nv_bfloat16*)(sm + SWL_OFF + off) = l;
        }
    }
    // zero A tile (4KB) and hs (4KB)
    for (int i = tid; i < 1024; i += GNTH) ((uint*)(sm + SA_OFF))[i] = 0;
    for (int i = tid; i < 1024; i += GNTH) ((uint*)(sm + HS_OFF))[i] = 0;
    const float bh = b_hh[tid];
    __syncthreads();

    // ldmatrix address precomputation
    const uint arow = lane & 15;
    const uint abase = arow * 256u;
    const uint asw = arow & 7;
    const uint aseg0 = (uint)(lane >> 4);
    const uint wrow = (uint)(G0 + ((lane & 16) >> 1) + (lane & 7));
    const uint wseg0 = (uint)((lane >> 3) & 1);

    // ---- Wh fragments -> registers (once)
    uint whr[8][8];
#pragma unroll
    for (int kt = 0; kt < 8; kt++) {
#pragma unroll
        for (int gg = 0; gg < 2; gg++) {
            uint row = wrow + gg * 16;
            uint seg = (uint)(kt * 2) + wseg0;
            uint woff = row * 256u + ((seg ^ (row & 7)) << 4);
            ldsm_x4(whr[kt][gg*4+0], whr[kt][gg*4+1], whr[kt][gg*4+2], whr[kt][gg*4+3],
                    sbase + SWH_OFF + woff);
        }
    }

    for (int t = 0; t < TT; t++) {
        float giv[NB];
#pragma unroll
        for (int b = 0; b < NB; b++)
            giv[b] = gi[((size_t)((b0 + b) * TT + t)) * G3 + tid];

        float acc[4][4];
#pragma unroll
        for (int ni = 0; ni < 4; ni++)
#pragma unroll
            for (int v = 0; v < 4; v++) acc[ni][v] = 0.f;

#pragma unroll
        for (int kt = 0; kt < 8; kt++) {
            uint aoff = abase + ((((uint)(kt * 2) + aseg0) ^ asw) << 4);
            uint a[4];
            ldsm_x4(a[0], a[1], a[2], a[3], sbase + SA_OFF + aoff);

            uint wl[8];
#pragma unroll
            for (int gg = 0; gg < 2; gg++) {
                uint row = wrow + gg * 16;
                uint seg = (uint)(kt * 2) + wseg0;
                uint woff = row * 256u + ((seg ^ (row & 7)) << 4);
                ldsm_x4(wl[gg*4+0], wl[gg*4+1], wl[gg*4+2], wl[gg*4+3],
                        sbase + SWL_OFF + woff);
            }
#pragma unroll
            for (int ni = 0; ni < 4; ni++) {
                mma_bf16(acc[ni], a, &whr[kt][ni*2]);
                mma_bf16(acc[ni], a, &wl[ni*2]);
            }
        }

        // gh[b] = D[row b] + D[row b+8]  -> sgh[b][G0..G0+31]
        {
            const int brow = lane >> 2;
            const int c = (lane & 3) * 2;
            float* p = sgh + brow * SGH_P + G0;
#pragma unroll
            for (int ni = 0; ni < 4; ni++) {
                float2 v = { acc[ni][0] + acc[ni][2], acc[ni][1] + acc[ni][3] };
                *(float2*)(p + ni * 8 + c) = v;
            }
        }
        __syncwarp();

        float ghv[NB];
#pragma unroll
        for (int b = 0; b < NB; b++)
            ghv[b] = sgh[b * SGH_P + tid] + bh;

        if (gtype == 0) {
#pragma unroll
            for (int b = 0; b < NB; b++)
                rb[b * HH + j] = 1.f / (1.f + expf(-(giv[b] + ghv[b])));
        } else if (gtype == 1) {
#pragma unroll
            for (int b = 0; b < NB; b++)
                zb[b * HH + j] = 1.f / (1.f + expf(-(giv[b] + ghv[b])));
        }
        __syncthreads();

        if (gtype == 2) {
            const int jsw = j & 7;
            const int seg = j >> 3;
#pragma unroll
            for (int b = 0; b < NB; b++) {
                float r = rb[b * HH + j];
                float z = zb[b * HH + j];
                float n = tanhf(giv[b] + r * ghv[b]);
                float hn = (1.f - z) * n + z * hs[b * HH + j];
                hs[b * HH + j] = hn;
                __nv_bfloat16 hh, hl;
                split_bf16(hn, hh, hl);
                int swo = ((seg ^ (b & 7)) << 4) + jsw * 2;
                *(__nv_bfloat16*)(sm + SA_OFF + b * 256 + swo)        = hh;
                *(__nv_bfloat16*)(sm + SA_OFF + (b + 8) * 256 + swo)  = hl;
                if (write_seq) {
                    size_t m = (size_t)((b0 + b) * TT + t) * HH + j;
                    seqh[m] = hh;
                    seql[m] = hl;
                }
            }
        }
        __syncthreads();
    }

    if (!write_seq && gtype == 2) {
#pragma unroll
        for (int b = 0; b < NB; b++)
            hlast_out[(b0 + b) * HH + j] = hs[b * HH + j];
    }
}

// ---------------------------------------------------------------------------
// head — Linear(128,64) -> ReLU -> Linear(64,1) -> Sigmoid
// ---------------------------------------------------------------------------
__global__ __launch_bounds__(64)
void head_kernel(const float* __restrict__ hlast, const float* __restrict__ W1,
                 const float* __restrict__ b1, const float* __restrict__ W2,
                 const float* __restrict__ b2, float* __restrict__ out)
{
    __shared__ float hsm[HH];
    __shared__ float partial[2];
    const int b = blockIdx.x, tid = threadIdx.x;

    hsm[tid]      = hlast[b * HH + tid];
    hsm[tid + 64] = hlast[b * HH + 64 + tid];
    __syncthreads();

    float acc = b1[tid];
#pragma unroll 4
    for (int k = 0; k < HH; k++)
        acc += hsm[k] * W1[tid * HH + k];
    float v = fmaxf(acc, 0.f) * W2[tid];

#pragma unroll
    for (int o = 16; o > 0; o >>= 1)
        v += __shfl_down_sync(0xffffffffu, v, o);
    if ((tid & 31) == 0) partial[tid >> 5] = v;
    __syncthreads();
    if (tid == 0)
        out[b] = 1.f / (1.f + expf(-(partial[0] + partial[1] + b2[0])));
}

// ---------------------------------------------------------------------------
// Launch
// ---------------------------------------------------------------------------
extern "C" void kernel_launch(void* const* d_in, const int* in_sizes, int n_in,
                              void* d_out, int out_size)
{
    (void)in_sizes; (void)n_in; (void)out_size;
    const float* x     = (const float*)d_in[0];
    const float* W_ih0 = (const float*)d_in[1];
    const float* W_hh0 = (const float*)d_in[2];
    const float* b_ih0 = (const float*)d_in[3];
    const float* b_hh0 = (const float*)d_in[4];
    const float* W_ih1 = (const float*)d_in[5];
    const float* W_hh1 = (const float*)d_in[6];
    const float* b_ih1 = (const float*)d_in[7];
    const float* b_hh1 = (const float*)d_in[8];
    const float* W1    = (const float*)d_in[9];
    const float* b1    = (const float*)d_in[10];
    const float* W2    = (const float*)d_in[11];
    const float* b2    = (const float*)d_in[12];
    float* out = (float*)d_out;

    float *gi, *hlast;
    __nv_bfloat16 *xh, *xl, *sh, *sl, *w0h, *w0l, *w1h, *w1l;
    cudaGetSymbolAddress((void**)&gi,    g_gi);
    cudaGetSymbolAddress((void**)&hlast, g_hlast);
    cudaGetSymbolAddress((void**)&xh,  g_xh);
    cudaGetSymbolAddress((void**)&xl,  g_xl);
    cudaGetSymbolAddress((void**)&sh,  g_sh);
    cudaGetSymbolAddress((void**)&sl,  g_sl);
    cudaGetSymbolAddress((void**)&w0h, g_w0h);
    cudaGetSymbolAddress((void**)&w0l, g_w0l);
    cudaGetSymbolAddress((void**)&w1h, g_w1h);
    cudaGetSymbolAddress((void**)&w1l, g_w1l);

    cudaFuncSetAttribute(gru_layer_tc, cudaFuncAttributeMaxDynamicSharedMemorySize,
                         GRU_SMEM);

    dim3 tgrid(MTOT / 128, G3 / 128);   // (2048, 3)

    prep_split_rows<<<MTOT / 8, 256>>>(x, xh, xl, MTOT, II, KP0);
    prep_split_rows<<<G3 / 8, 256>>>(W_ih0, w0h, w0l, G3, II, KP0);
    prep_split_rows<<<G3 / 8, 256>>>(W_ih1, w1h, w1l, G3, HH, HH);

    gemm_tc2<<<tgrid, 256>>>(xh, xl, w0h, w0l, b_ih0, gi, KP0);
    gru_layer_tc<<<BATCH / NB, GNTH, GRU_SMEM>>>(gi, W_hh0, b_hh0, sh, sl, nullptr, 1);
    gemm_tc2<<<tgrid, 256>>>(sh, sl, w1h, w1l, b_ih1, gi, HH);
    gru_layer_tc<<<BATCH / NB, GNTH, GRU_SMEM>>>(gi, W_hh1, b_hh1, nullptr, nullptr, hlast, 0);
    head_kernel<<<BATCH, 64>>>(hlast, W1, b1, W2, b2, out);
}

// round 9
// speedup vs baseline: 1.8281x; 1.1683x over previous
#include <cuda_runtime.h>
#include <cuda_bf16.h>
#include <math.h>

typedef unsigned long long ull;
typedef unsigned int uint;
typedef unsigned short ushort;

// Problem constants
#define BATCH 1024
#define TT    256
#define II    153
#define KP0   160        // II padded to multiple of 16
#define HH    128
#define G3    384
#define MTOT  (BATCH*TT)   // 262144

// ---------------------------------------------------------------------------
// Scratch (device globals — no runtime allocation allowed)
// ---------------------------------------------------------------------------
__device__ float g_gi[(size_t)MTOT * G3];                 // ~403 MB
__device__ __nv_bfloat16 g_xh[(size_t)MTOT * KP0];
__device__ __nv_bfloat16 g_xl[(size_t)MTOT * KP0];
__device__ __nv_bfloat16 g_sh[(size_t)MTOT * HH];
__device__ __nv_bfloat16 g_sl[(size_t)MTOT * HH];
__device__ __nv_bfloat16 g_w0h[G3 * KP0], g_w0l[G3 * KP0];
__device__ __nv_bfloat16 g_w1h[G3 * HH],  g_w1l[G3 * HH];
__device__ float g_hlast[BATCH * HH];

// ---------------------------------------------------------------------------
// helpers
// ---------------------------------------------------------------------------
__device__ __forceinline__ void split_bf16(float a, __nv_bfloat16& h, __nv_bfloat16& l) {
    h = __float2bfloat16(a);
    l = __float2bfloat16(a - __bfloat162float(h));
}
__device__ __forceinline__ void ldsm_x4(uint& r0, uint& r1, uint& r2, uint& r3, uint addr) {
    asm volatile("ldmatrix.sync.aligned.m8n8.x4.shared.b16 {%0,%1,%2,%3}, [%4];"
        : "=r"(r0), "=r"(r1), "=r"(r2), "=r"(r3) : "r"(addr));
}
__device__ __forceinline__ void mma_bf16(float* d, const uint* a, const uint* b) {
    asm volatile("mma.sync.aligned.m16n8k16.row.col.f32.bf16.bf16.f32 "
        "{%0,%1,%2,%3}, {%4,%5,%6,%7}, {%8,%9}, {%0,%1,%2,%3};"
        : "+f"(d[0]), "+f"(d[1]), "+f"(d[2]), "+f"(d[3])
        : "r"(a[0]), "r"(a[1]), "r"(a[2]), "r"(a[3]), "r"(b[0]), "r"(b[1]));
}
__device__ __forceinline__ void cp16(uint dst, const void* src) {
    asm volatile("cp.async.cg.shared.global [%0], [%1], 16;" :: "r"(dst), "l"(src));
}
#define CP_COMMIT() asm volatile("cp.async.commit_group;")
#define CP_WAIT0()  asm volatile("cp.async.wait_group 0;")
#define CP_WAIT1()  asm volatile("cp.async.wait_group 1;")

// fast saturating sigmoid / tanh (MUFU ex2 + rcp; safe at +-inf)
__device__ __forceinline__ float fsig(float x) {
    return __fdividef(1.f, 1.f + __expf(-x));
}
__device__ __forceinline__ float ftanh(float x) {
    float e2 = __expf(2.f * x);
    return 1.f - __fdividef(2.f, e2 + 1.f);
}

// ---------------------------------------------------------------------------
// Prepass: split fp32 [rows,Kin] -> bf16 hi/lo [rows,Kout], zero-padded.
// ---------------------------------------------------------------------------
__global__ void prep_split_rows(const float* __restrict__ in,
                                __nv_bfloat16* __restrict__ oh,
                                __nv_bfloat16* __restrict__ ol,
                                int rows, int Kin, int Kout)
{
    const int warp = (blockIdx.x * blockDim.x + threadIdx.x) >> 5;
    const int lane = threadIdx.x & 31;
    if (warp >= rows) return;
    const float* src = in + (size_t)warp * Kin;
    const size_t o = (size_t)warp * Kout;
    for (int k = lane; k < Kout; k += 32) {
        float v = (k < Kin) ? src[k] : 0.f;
        __nv_bfloat16 h, l;
        split_bf16(v, h, l);
        oh[o + k] = h;
        ol[o + k] = l;
    }
}

// ---------------------------------------------------------------------------
// Pure-bf16 tensor-core GEMM, 3-term split, 3-stage cp.async pipeline.
// Grid = (3 n-blocks, 2048 m-blocks): consecutive CTAs share the same A
// m-tile -> A reads hit L2 (3x DRAM traffic cut vs x-major m grid).
// ---------------------------------------------------------------------------
#define TLD 40
#define GBUF (128 * TLD * 2)            // bytes per buffer per matrix (10240)
#define GEMM_SMEM (6 * GBUF)            // 3 stages x (A+B) = 61440

__global__ __launch_bounds__(256, 2)
void gemm_tc3(const __nv_bfloat16* __restrict__ Ah, const __nv_bfloat16* __restrict__ Al,
              const __nv_bfloat16* __restrict__ Bh, const __nv_bfloat16* __restrict__ Bl,
              const float* __restrict__ bias, float* __restrict__ C, int K)
{
    extern __shared__ __align__(16) char smem_raw[];
    const uint sa0 = (uint)__cvta_generic_to_shared(smem_raw);
    const uint sb0 = sa0 + 3 * GBUF;

    const int tid  = threadIdx.x;
    const int warp = tid >> 5;
    const int lane = tid & 31;
    const size_t m0 = (size_t)blockIdx.y * 128;
    const int n0 = blockIdx.x * 128;
    const int wm = (warp >> 2) * 64;
    const int wn = (warp & 3) * 32;

    float acc[4][4][4];
#pragma unroll
    for (int i = 0; i < 4; i++)
#pragma unroll
        for (int j = 0; j < 4; j++)
#pragma unroll
            for (int v = 0; v < 4; v++) acc[i][j][v] = 0.f;

    const int KT = K >> 4;

    // cp.async seg decode: 4 segs/thread
    const __nv_bfloat16* srcs[4];
    uint dsts[4];
    size_t srcoff[4];
#pragma unroll
    for (int i = 0; i < 4; i++) {
        int s   = tid + 256 * i;
        int mat = s >> 9;
        int r   = (s >> 2) & 127;
        int seg = s & 3;
        const __nv_bfloat16* base =
            mat ? (seg < 2 ? Bh : Bl) : (seg < 2 ? Ah : Al);
        size_t row = mat ? (size_t)(n0 + r) : (m0 + r);
        srcs[i]   = base;
        srcoff[i] = row * K + (seg & 1) * 8;
        dsts[i]   = (mat ? sb0 : sa0) + (uint)(r * 80 + seg * 16);
    }

    // prologue: tiles 0,1
#pragma unroll
    for (int i = 0; i < 4; i++)
        cp16(dsts[i], srcs[i] + srcoff[i]);
    CP_COMMIT();
    if (1 < KT) {
#pragma unroll
        for (int i = 0; i < 4; i++)
            cp16(dsts[i] + GBUF, srcs[i] + srcoff[i] + 16);
        CP_COMMIT();
    }

    int buf = 0;
    for (int kt = 0; kt < KT; kt++) {
        if (kt + 1 < KT) { CP_WAIT1(); } else { CP_WAIT0(); }
        __syncthreads();

        if (kt + 2 < KT) {
            uint doff = (uint)((kt + 2) % 3) * GBUF;
            size_t koff = (size_t)(kt + 2) * 16;
#pragma unroll
            for (int i = 0; i < 4; i++)
                cp16(dsts[i] + doff, srcs[i] + srcoff[i] + koff);
            CP_COMMIT();
        }

        uint sa_base = sa0 + buf * GBUF;
        uint sb_base = sb0 + buf * GBUF;

        uint bhf[8], blf[8];
#pragma unroll
        for (int g = 0; g < 2; g++) {
            int nrow = wn + g * 16 + ((lane & 16) >> 1) + (lane & 7);
            int kcol = ((lane >> 3) & 1) * 8;
            ldsm_x4(bhf[g*4+0], bhf[g*4+1], bhf[g*4+2], bhf[g*4+3],
                    sb_base + (uint)(nrow * TLD + kcol) * 2u);
            ldsm_x4(blf[g*4+0], blf[g*4+1], blf[g*4+2], blf[g*4+3],
                    sb_base + (uint)(nrow * TLD + 16 + kcol) * 2u);
        }

#pragma unroll
        for (int mi = 0; mi < 4; mi++) {
            int arow = wm + mi * 16 + (lane & 15);
            int acol = ((lane >> 4) & 1) * 8;
            uint ah[4], al[4];
            ldsm_x4(ah[0], ah[1], ah[2], ah[3],
                    sa_base + (uint)(arow * TLD + acol) * 2u);
            ldsm_x4(al[0], al[1], al[2], al[3],
                    sa_base + (uint)(arow * TLD + 16 + acol) * 2u);
#pragma unroll
            for (int ni = 0; ni < 4; ni++) {
                mma_bf16(acc[mi][ni], ah, &bhf[ni*2]);
                mma_bf16(acc[mi][ni], ah, &blf[ni*2]);
                mma_bf16(acc[mi][ni], al, &bhf[ni*2]);
            }
        }
        buf = (buf + 1) % 3;
    }

    const int r = lane >> 2;
    const int c2 = (lane & 3) * 2;
#pragma unroll
    for (int mi = 0; mi < 4; mi++) {
#pragma unroll
        for (int ni = 0; ni < 4; ni++) {
            int n = n0 + wn + ni * 8 + c2;
            float b0 = bias[n], b1 = bias[n + 1];
            size_t m = m0 + wm + mi * 16 + r;
            float2 v0 = { acc[mi][ni][0] + b0, acc[mi][ni][1] + b1 };
            float2 v1 = { acc[mi][ni][2] + b0, acc[mi][ni][3] + b1 };
            *(float2*)&C[m * G3 + n]       = v0;
            *(float2*)&C[(m + 8) * G3 + n] = v1;
        }
    }
}

// ---------------------------------------------------------------------------
// GRU recurrence on tensor cores (R8 structure, fast-math gate phase).
// ---------------------------------------------------------------------------
#define NB 8
#define GNTH 384
#define SWH_OFF 0
#define SWL_OFF 98304
#define SA_OFF  196608   // 16 rows x 256B (rows 0-7 hi, 8-15 lo)
#define HS_OFF  200704
#define SGH_OFF 204800
#define RB_OFF  217408
#define ZB_OFF  221504
#define GRU_SMEM 225600
#define SGH_P   394

__global__ __launch_bounds__(GNTH)
void gru_layer_tc(const float* __restrict__ gi,
                  const float* __restrict__ W_hh,
                  const float* __restrict__ b_hh,
                  __nv_bfloat16* __restrict__ seqh,
                  __nv_bfloat16* __restrict__ seql,
                  float* __restrict__ hlast_out,
                  int write_seq)
{
    extern __shared__ char sm[];
    float* hs  = (float*)(sm + HS_OFF);
    float* sgh = (float*)(sm + SGH_OFF);
    float* rb  = (float*)(sm + RB_OFF);
    float* zb  = (float*)(sm + ZB_OFF);
    const uint sbase = (uint)__cvta_generic_to_shared(sm);

    const int tid  = threadIdx.x;
    const int lane = tid & 31;
    const int warp = tid >> 5;
    const int G0   = warp * 32;
    const int b0   = blockIdx.x * NB;
    const int j    = tid & 127;
    const int gtype = tid >> 7;

    {
        const int gsw = tid & 7;
#pragma unroll 4
        for (int k = 0; k < HH; k++) {
            float w = W_hh[(size_t)tid * HH + k];
            __nv_bfloat16 h, l;
            split_bf16(w, h, l);
            int off = tid * 256 + (((k >> 3) ^ gsw) << 4) + (k & 7) * 2;
            *(__nv_bfloat16*)(sm + SWH_OFF + off) = h;
            *(__nv_bfloat16*)(sm + SWL_OFF + off) = l;
        }
    }
    for (int i = tid; i < 1024; i += GNTH) ((uint*)(sm + SA_OFF))[i] = 0;
    for (int i = tid; i < 1024; i += GNTH) ((uint*)(sm + HS_OFF))[i] = 0;
    const float bh = b_hh[tid];
    __syncthreads();

    const uint arow = lane & 15;
    const uint abase = arow * 256u;
    const uint asw = arow & 7;
    const uint aseg0 = (uint)(lane >> 4);
    const uint wrow = (uint)(G0 + ((lane & 16) >> 1) + (lane & 7));
    const uint wseg0 = (uint)((lane >> 3) & 1);

    uint whr[8][8];
#pragma unroll
    for (int kt = 0; kt < 8; kt++) {
#pragma unroll
        for (int gg = 0; gg < 2; gg++) {
            uint row = wrow + gg * 16;
            uint seg = (uint)(kt * 2) + wseg0;
            uint woff = row * 256u + ((seg ^ (row & 7)) << 4);
            ldsm_x4(whr[kt][gg*4+0], whr[kt][gg*4+1], whr[kt][gg*4+2], whr[kt][gg*4+3],
                    sbase + SWH_OFF + woff);
        }
    }

    for (int t = 0; t < TT; t++) {
        float giv[NB];
#pragma unroll
        for (int b = 0; b < NB; b++)
            giv[b] = gi[((size_t)((b0 + b) * TT + t)) * G3 + tid];

        float acc[4][4];
#pragma unroll
        for (int ni = 0; ni < 4; ni++)
#pragma unroll
            for (int v = 0; v < 4; v++) acc[ni][v] = 0.f;

#pragma unroll
        for (int kt = 0; kt < 8; kt++) {
            uint aoff = abase + ((((uint)(kt * 2) + aseg0) ^ asw) << 4);
            uint a[4];
            ldsm_x4(a[0], a[1], a[2], a[3], sbase + SA_OFF + aoff);

            uint wl[8];
#pragma unroll
            for (int gg = 0; gg < 2; gg++) {
                uint row = wrow + gg * 16;
                uint seg = (uint)(kt * 2) + wseg0;
                uint woff = row * 256u + ((seg ^ (row & 7)) << 4);
                ldsm_x4(wl[gg*4+0], wl[gg*4+1], wl[gg*4+2], wl[gg*4+3],
                        sbase + SWL_OFF + woff);
            }
#pragma unroll
            for (int ni = 0; ni < 4; ni++) {
                mma_bf16(acc[ni], a, &whr[kt][ni*2]);
                mma_bf16(acc[ni], a, &wl[ni*2]);
            }
        }

        {
            const int brow = lane >> 2;
            const int c = (lane & 3) * 2;
            float* p = sgh + brow * SGH_P + G0;
#pragma unroll
            for (int ni = 0; ni < 4; ni++) {
                float2 v = { acc[ni][0] + acc[ni][2], acc[ni][1] + acc[ni][3] };
                *(float2*)(p + ni * 8 + c) = v;
            }
        }
        __syncwarp();

        float ghv[NB];
#pragma unroll
        for (int b = 0; b < NB; b++)
            ghv[b] = sgh[b * SGH_P + tid] + bh;

        if (gtype == 0) {
#pragma unroll
            for (int b = 0; b < NB; b++)
                rb[b * HH + j] = fsig(giv[b] + ghv[b]);
        } else if (gtype == 1) {
#pragma unroll
            for (int b = 0; b < NB; b++)
                zb[b * HH + j] = fsig(giv[b] + ghv[b]);
        }
        __syncthreads();

        if (gtype == 2) {
            const int jsw = j & 7;
            const int seg = j >> 3;
#pragma unroll
            for (int b = 0; b < NB; b++) {
                float r = rb[b * HH + j];
                float z = zb[b * HH + j];
                float n = ftanh(giv[b] + r * ghv[b]);
                float hn = (1.f - z) * n + z * hs[b * HH + j];
                hs[b * HH + j] = hn;
                __nv_bfloat16 hh, hl;
                split_bf16(hn, hh, hl);
                int swo = ((seg ^ (b & 7)) << 4) + jsw * 2;
                *(__nv_bfloat16*)(sm + SA_OFF + b * 256 + swo)        = hh;
                *(__nv_bfloat16*)(sm + SA_OFF + (b + 8) * 256 + swo)  = hl;
                if (write_seq) {
                    size_t m = (size_t)((b0 + b) * TT + t) * HH + j;
                    seqh[m] = hh;
                    seql[m] = hl;
                }
            }
        }
        __syncthreads();
    }

    if (!write_seq && gtype == 2) {
#pragma unroll
        for (int b = 0; b < NB; b++)
            hlast_out[(b0 + b) * HH + j] = hs[b * HH + j];
    }
}

// ---------------------------------------------------------------------------
// head
// ---------------------------------------------------------------------------
__global__ __launch_bounds__(64)
void head_kernel(const float* __restrict__ hlast, const float* __restrict__ W1,
                 const float* __restrict__ b1, const float* __restrict__ W2,
                 const float* __restrict__ b2, float* __restrict__ out)
{
    __shared__ float hsm[HH];
    __shared__ float partial[2];
    const int b = blockIdx.x, tid = threadIdx.x;

    hsm[tid]      = hlast[b * HH + tid];
    hsm[tid + 64] = hlast[b * HH + 64 + tid];
    __syncthreads();

    float acc = b1[tid];
#pragma unroll 4
    for (int k = 0; k < HH; k++)
        acc += hsm[k] * W1[tid * HH + k];
    float v = fmaxf(acc, 0.f) * W2[tid];

#pragma unroll
    for (int o = 16; o > 0; o >>= 1)
        v += __shfl_down_sync(0xffffffffu, v, o);
    if ((tid & 31) == 0) partial[tid >> 5] = v;
    __syncthreads();
    if (tid == 0)
        out[b] = 1.f / (1.f + expf(-(partial[0] + partial[1] + b2[0])));
}

// ---------------------------------------------------------------------------
// Launch
// ---------------------------------------------------------------------------
extern "C" void kernel_launch(void* const* d_in, const int* in_sizes, int n_in,
                              void* d_out, int out_size)
{
    (void)in_sizes; (void)n_in; (void)out_size;
    const float* x     = (const float*)d_in[0];
    const float* W_ih0 = (const float*)d_in[1];
    const float* W_hh0 = (const float*)d_in[2];
    const float* b_ih0 = (const float*)d_in[3];
    const float* b_hh0 = (const float*)d_in[4];
    const float* W_ih1 = (const float*)d_in[5];
    const float* W_hh1 = (const float*)d_in[6];
    const float* b_ih1 = (const float*)d_in[7];
    const float* b_hh1 = (const float*)d_in[8];
    const float* W1    = (const float*)d_in[9];
    const float* b1    = (const float*)d_in[10];
    const float* W2    = (const float*)d_in[11];
    const float* b2    = (const float*)d_in[12];
    float* out = (float*)d_out;

    float *gi, *hlast;
    __nv_bfloat16 *xh, *xl, *sh, *sl, *w0h, *w0l, *w1h, *w1l;
    cudaGetSymbolAddress((void**)&gi,    g_gi);
    cudaGetSymbolAddress((void**)&hlast, g_hlast);
    cudaGetSymbolAddress((void**)&xh,  g_xh);
    cudaGetSymbolAddress((void**)&xl,  g_xl);
    cudaGetSymbolAddress((void**)&sh,  g_sh);
    cudaGetSymbolAddress((void**)&sl,  g_sl);
    cudaGetSymbolAddress((void**)&w0h, g_w0h);
    cudaGetSymbolAddress((void**)&w0l, g_w0l);
    cudaGetSymbolAddress((void**)&w1h, g_w1h);
    cudaGetSymbolAddress((void**)&w1l, g_w1l);

    cudaFuncSetAttribute(gru_layer_tc, cudaFuncAttributeMaxDynamicSharedMemorySize,
                         GRU_SMEM);
    cudaFuncSetAttribute(gemm_tc3, cudaFuncAttributeMaxDynamicSharedMemorySize,
                         GEMM_SMEM);

    dim3 tgrid(G3 / 128, MTOT / 128);   // (3, 2048): n-blocks adjacent -> A L2 reuse

    prep_split_rows<<<MTOT / 8, 256>>>(x, xh, xl, MTOT, II, KP0);
    prep_split_rows<<<G3 / 8, 256>>>(W_ih0, w0h, w0l, G3, II, KP0);
    prep_split_rows<<<G3 / 8, 256>>>(W_ih1, w1h, w1l, G3, HH, HH);

    gemm_tc3<<<tgrid, 256, GEMM_SMEM>>>(xh, xl, w0h, w0l, b_ih0, gi, KP0);
    gru_layer_tc<<<BATCH / NB, GNTH, GRU_SMEM>>>(gi, W_hh0, b_hh0, sh, sl, nullptr, 1);
    gemm_tc3<<<tgrid, 256, GEMM_SMEM>>>(sh, sl, w1h, w1l, b_ih1, gi, HH);
    gru_layer_tc<<<BATCH / NB, GNTH, GRU_SMEM>>>(gi, W_hh1, b_hh1, nullptr, nullptr, hlast, 0);
    head_kernel<<<BATCH, 64>>>(hlast, W1, b1, W2, b2, out);
}

// round 10
// speedup vs baseline: 1.8283x; 1.0001x over previous
#include <cuda_runtime.h>
#include <cuda_bf16.h>
#include <math.h>

typedef unsigned long long ull;
typedef unsigned int uint;
typedef unsigned short ushort;

// Problem constants
#define BATCH 1024
#define TT    256
#define II    153
#define KP0   160        // II padded to multiple of 16
#define HH    128
#define G3    384
#define MTOT  (BATCH*TT)   // 262144

// ---------------------------------------------------------------------------
// Scratch (device globals — no runtime allocation allowed)
// ---------------------------------------------------------------------------
__device__ float g_gi[(size_t)MTOT * G3];                 // ~403 MB
__device__ __nv_bfloat16 g_xh[(size_t)MTOT * KP0];
__device__ __nv_bfloat16 g_xl[(size_t)MTOT * KP0];
__device__ __nv_bfloat16 g_sh[(size_t)MTOT * HH];
__device__ __nv_bfloat16 g_sl[(size_t)MTOT * HH];
__device__ __nv_bfloat16 g_w0h[G3 * KP0], g_w0l[G3 * KP0];
__device__ __nv_bfloat16 g_w1h[G3 * HH],  g_w1l[G3 * HH];
__device__ float g_hlast[BATCH * HH];

// ---------------------------------------------------------------------------
// helpers
// ---------------------------------------------------------------------------
__device__ __forceinline__ void split_bf16(float a, __nv_bfloat16& h, __nv_bfloat16& l) {
    h = __float2bfloat16(a);
    l = __float2bfloat16(a - __bfloat162float(h));
}
__device__ __forceinline__ void ldsm_x4(uint& r0, uint& r1, uint& r2, uint& r3, uint addr) {
    asm volatile("ldmatrix.sync.aligned.m8n8.x4.shared.b16 {%0,%1,%2,%3}, [%4];"
        : "=r"(r0), "=r"(r1), "=r"(r2), "=r"(r3) : "r"(addr));
}
__device__ __forceinline__ void mma_bf16(float* d, const uint* a, const uint* b) {
    asm volatile("mma.sync.aligned.m16n8k16.row.col.f32.bf16.bf16.f32 "
        "{%0,%1,%2,%3}, {%4,%5,%6,%7}, {%8,%9}, {%0,%1,%2,%3};"
        : "+f"(d[0]), "+f"(d[1]), "+f"(d[2]), "+f"(d[3])
        : "r"(a[0]), "r"(a[1]), "r"(a[2]), "r"(a[3]), "r"(b[0]), "r"(b[1]));
}
__device__ __forceinline__ void cp16(uint dst, const void* src) {
    asm volatile("cp.async.cg.shared.global [%0], [%1], 16;" :: "r"(dst), "l"(src));
}
#define CP_COMMIT() asm volatile("cp.async.commit_group;")
#define CP_WAIT0()  asm volatile("cp.async.wait_group 0;")
#define CP_WAIT1()  asm volatile("cp.async.wait_group 1;")

// fast saturating sigmoid / tanh (MUFU ex2 + rcp; safe at +-inf)
__device__ __forceinline__ float fsig(float x) {
    return __fdividef(1.f, 1.f + __expf(-x));
}
__device__ __forceinline__ float ftanh(float x) {
    float e2 = __expf(2.f * x);
    return 1.f - __fdividef(2.f, e2 + 1.f);
}

// ---------------------------------------------------------------------------
// Prepass: split fp32 [rows,Kin] -> bf16 hi/lo [rows,Kout], zero-padded.
// ---------------------------------------------------------------------------
__global__ void prep_split_rows(const float* __restrict__ in,
                                __nv_bfloat16* __restrict__ oh,
                                __nv_bfloat16* __restrict__ ol,
                                int rows, int Kin, int Kout)
{
    const int warp = (blockIdx.x * blockDim.x + threadIdx.x) >> 5;
    const int lane = threadIdx.x & 31;
    if (warp >= rows) return;
    const float* src = in + (size_t)warp * Kin;
    const size_t o = (size_t)warp * Kout;
    for (int k = lane; k < Kout; k += 32) {
        float v = (k < Kin) ? src[k] : 0.f;
        __nv_bfloat16 h, l;
        split_bf16(v, h, l);
        oh[o + k] = h;
        ol[o + k] = l;
    }
}

// ---------------------------------------------------------------------------
// Pure-bf16 tensor-core GEMM, 3-term split, 3-stage cp.async pipeline.
// Grid = (3 n-blocks, 2048 m-blocks): consecutive CTAs share the same A
// m-tile -> A reads hit L2 (3x DRAM traffic cut vs x-major m grid).
// ---------------------------------------------------------------------------
#define TLD 40
#define GBUF (128 * TLD * 2)            // bytes per buffer per matrix (10240)
#define GEMM_SMEM (6 * GBUF)            // 3 stages x (A+B) = 61440

__global__ __launch_bounds__(256, 2)
void gemm_tc3(const __nv_bfloat16* __restrict__ Ah, const __nv_bfloat16* __restrict__ Al,
              const __nv_bfloat16* __restrict__ Bh, const __nv_bfloat16* __restrict__ Bl,
              const float* __restrict__ bias, float* __restrict__ C, int K)
{
    extern __shared__ __align__(16) char smem_raw[];
    const uint sa0 = (uint)__cvta_generic_to_shared(smem_raw);
    const uint sb0 = sa0 + 3 * GBUF;

    const int tid  = threadIdx.x;
    const int warp = tid >> 5;
    const int lane = tid & 31;
    const size_t m0 = (size_t)blockIdx.y * 128;
    const int n0 = blockIdx.x * 128;
    const int wm = (warp >> 2) * 64;
    const int wn = (warp & 3) * 32;

    float acc[4][4][4];
#pragma unroll
    for (int i = 0; i < 4; i++)
#pragma unroll
        for (int j = 0; j < 4; j++)
#pragma unroll
            for (int v = 0; v < 4; v++) acc[i][j][v] = 0.f;

    const int KT = K >> 4;

    // cp.async seg decode: 4 segs/thread
    const __nv_bfloat16* srcs[4];
    uint dsts[4];
    size_t srcoff[4];
#pragma unroll
    for (int i = 0; i < 4; i++) {
        int s   = tid + 256 * i;
        int mat = s >> 9;
        int r   = (s >> 2) & 127;
        int seg = s & 3;
        const __nv_bfloat16* base =
            mat ? (seg < 2 ? Bh : Bl) : (seg < 2 ? Ah : Al);
        size_t row = mat ? (size_t)(n0 + r) : (m0 + r);
        srcs[i]   = base;
        srcoff[i] = row * K + (seg & 1) * 8;
        dsts[i]   = (mat ? sb0 : sa0) + (uint)(r * 80 + seg * 16);
    }

    // prologue: tiles 0,1
#pragma unroll
    for (int i = 0; i < 4; i++)
        cp16(dsts[i], srcs[i] + srcoff[i]);
    CP_COMMIT();
    if (1 < KT) {
#pragma unroll
        for (int i = 0; i < 4; i++)
            cp16(dsts[i] + GBUF, srcs[i] + srcoff[i] + 16);
        CP_COMMIT();
    }

    int buf = 0;
    for (int kt = 0; kt < KT; kt++) {
        if (kt + 1 < KT) { CP_WAIT1(); } else { CP_WAIT0(); }
        __syncthreads();

        if (kt + 2 < KT) {
            uint doff = (uint)((kt + 2) % 3) * GBUF;
            size_t koff = (size_t)(kt + 2) * 16;
#pragma unroll
            for (int i = 0; i < 4; i++)
                cp16(dsts[i] + doff, srcs[i] + srcoff[i] + koff);
            CP_COMMIT();
        }

        uint sa_base = sa0 + buf * GBUF;
        uint sb_base = sb0 + buf * GBUF;

        uint bhf[8], blf[8];
#pragma unroll
        for (int g = 0; g < 2; g++) {
            int nrow = wn + g * 16 + ((lane & 16) >> 1) + (lane & 7);
            int kcol = ((lane >> 3) & 1) * 8;
            ldsm_x4(bhf[g*4+0], bhf[g*4+1], bhf[g*4+2], bhf[g*4+3],
                    sb_base + (uint)(nrow * TLD + kcol) * 2u);
            ldsm_x4(blf[g*4+0], blf[g*4+1], blf[g*4+2], blf[g*4+3],
                    sb_base + (uint)(nrow * TLD + 16 + kcol) * 2u);
        }

#pragma unroll
        for (int mi = 0; mi < 4; mi++) {
            int arow = wm + mi * 16 + (lane & 15);
            int acol = ((lane >> 4) & 1) * 8;
            uint ah[4], al[4];
            ldsm_x4(ah[0], ah[1], ah[2], ah[3],
                    sa_base + (uint)(arow * TLD + acol) * 2u);
            ldsm_x4(al[0], al[1], al[2], al[3],
                    sa_base + (uint)(arow * TLD + 16 + acol) * 2u);
#pragma unroll
            for (int ni = 0; ni < 4; ni++) {
                mma_bf16(acc[mi][ni], ah, &bhf[ni*2]);
                mma_bf16(acc[mi][ni], ah, &blf[ni*2]);
                mma_bf16(acc[mi][ni], al, &bhf[ni*2]);
            }
        }
        buf = (buf + 1) % 3;
    }

    const int r = lane >> 2;
    const int c2 = (lane & 3) * 2;
#pragma unroll
    for (int mi = 0; mi < 4; mi++) {
#pragma unroll
        for (int ni = 0; ni < 4; ni++) {
            int n = n0 + wn + ni * 8 + c2;
            float b0 = bias[n], b1 = bias[n + 1];
            size_t m = m0 + wm + mi * 16 + r;
            float2 v0 = { acc[mi][ni][0] + b0, acc[mi][ni][1] + b1 };
            float2 v1 = { acc[mi][ni][2] + b0, acc[mi][ni][3] + b1 };
            *(float2*)&C[m * G3 + n]       = v0;
            *(float2*)&C[(m + 8) * G3 + n] = v1;
        }
    }
}

// ---------------------------------------------------------------------------
// GRU recurrence on tensor cores (R8 structure, fast-math gate phase).
// ---------------------------------------------------------------------------
#define NB 8
#define GNTH 384
#define SWH_OFF 0
#define SWL_OFF 98304
#define SA_OFF  196608   // 16 rows x 256B (rows 0-7 hi, 8-15 lo)
#define HS_OFF  200704
#define SGH_OFF 204800
#define RB_OFF  217408
#define ZB_OFF  221504
#define GRU_SMEM 225600
#define SGH_P   394

__global__ __launch_bounds__(GNTH)
void gru_layer_tc(const float* __restrict__ gi,
                  const float* __restrict__ W_hh,
                  const float* __restrict__ b_hh,
                  __nv_bfloat16* __restrict__ seqh,
                  __nv_bfloat16* __restrict__ seql,
                  float* __restrict__ hlast_out,
                  int write_seq)
{
    extern __shared__ char sm[];
    float* hs  = (float*)(sm + HS_OFF);
    float* sgh = (float*)(sm + SGH_OFF);
    float* rb  = (float*)(sm + RB_OFF);
    float* zb  = (float*)(sm + ZB_OFF);
    const uint sbase = (uint)__cvta_generic_to_shared(sm);

    const int tid  = threadIdx.x;
    const int lane = tid & 31;
    const int warp = tid >> 5;
    const int G0   = warp * 32;
    const int b0   = blockIdx.x * NB;
    const int j    = tid & 127;
    const int gtype = tid >> 7;

    {
        const int gsw = tid & 7;
#pragma unroll 4
        for (int k = 0; k < HH; k++) {
            float w = W_hh[(size_t)tid * HH + k];
            __nv_bfloat16 h, l;
            split_bf16(w, h, l);
            int off = tid * 256 + (((k >> 3) ^ gsw) << 4) + (k & 7) * 2;
            *(__nv_bfloat16*)(sm + SWH_OFF + off) = h;
            *(__nv_bfloat16*)(sm + SWL_OFF + off) = l;
        }
    }
    for (int i = tid; i < 1024; i += GNTH) ((uint*)(sm + SA_OFF))[i] = 0;
    for (int i = tid; i < 1024; i += GNTH) ((uint*)(sm + HS_OFF))[i] = 0;
    const float bh = b_hh[tid];
    __syncthreads();

    const uint arow = lane & 15;
    const uint abase = arow * 256u;
    const uint asw = arow & 7;
    const uint aseg0 = (uint)(lane >> 4);
    const uint wrow = (uint)(G0 + ((lane & 16) >> 1) + (lane & 7));
    const uint wseg0 = (uint)((lane >> 3) & 1);

    uint whr[8][8];
#pragma unroll
    for (int kt = 0; kt < 8; kt++) {
#pragma unroll
        for (int gg = 0; gg < 2; gg++) {
            uint row = wrow + gg * 16;
            uint seg = (uint)(kt * 2) + wseg0;
            uint woff = row * 256u + ((seg ^ (row & 7)) << 4);
            ldsm_x4(whr[kt][gg*4+0], whr[kt][gg*4+1], whr[kt][gg*4+2], whr[kt][gg*4+3],
                    sbase + SWH_OFF + woff);
        }
    }

    for (int t = 0; t < TT; t++) {
        float giv[NB];
#pragma unroll
        for (int b = 0; b < NB; b++)
            giv[b] = gi[((size_t)((b0 + b) * TT + t)) * G3 + tid];

        float acc[4][4];
#pragma unroll
        for (int ni = 0; ni < 4; ni++)
#pragma unroll
            for (int v = 0; v < 4; v++) acc[ni][v] = 0.f;

#pragma unroll
        for (int kt = 0; kt < 8; kt++) {
            uint aoff = abase + ((((uint)(kt * 2) + aseg0) ^ asw) << 4);
            uint a[4];
            ldsm_x4(a[0], a[1], a[2], a[3], sbase + SA_OFF + aoff);

            uint wl[8];
#pragma unroll
            for (int gg = 0; gg < 2; gg++) {
                uint row = wrow + gg * 16;
                uint seg = (uint)(kt * 2) + wseg0;
                uint woff = row * 256u + ((seg ^ (row & 7)) << 4);
                ldsm_x4(wl[gg*4+0], wl[gg*4+1], wl[gg*4+2], wl[gg*4+3],
                        sbase + SWL_OFF + woff);
            }
#pragma unroll
            for (int ni = 0; ni < 4; ni++) {
                mma_bf16(acc[ni], a, &whr[kt][ni*2]);
                mma_bf16(acc[ni], a, &wl[ni*2]);
            }
        }

        {
            const int brow = lane >> 2;
            const int c = (lane & 3) * 2;
            float* p = sgh + brow * SGH_P + G0;
#pragma unroll
            for (int ni = 0; ni < 4; ni++) {
                float2 v = { acc[ni][0] + acc[ni][2], acc[ni][1] + acc[ni][3] };
                *(float2*)(p + ni * 8 + c) = v;
            }
        }
        __syncwarp();

        float ghv[NB];
#pragma unroll
        for (int b = 0; b < NB; b++)
            ghv[b] = sgh[b * SGH_P + tid] + bh;

        if (gtype == 0) {
#pragma unroll
            for (int b = 0; b < NB; b++)
                rb[b * HH + j] = fsig(giv[b] + ghv[b]);
        } else if (gtype == 1) {
#pragma unroll
            for (int b = 0; b < NB; b++)
                zb[b * HH + j] = fsig(giv[b] + ghv[b]);
        }
        __syncthreads();

        if (gtype == 2) {
            const int jsw = j & 7;
            const int seg = j >> 3;
#pragma unroll
            for (int b = 0; b < NB; b++) {
                float r = rb[b * HH + j];
                float z = zb[b * HH + j];
                float n = ftanh(giv[b] + r * ghv[b]);
                float hn = (1.f - z) * n + z * hs[b * HH + j];
                hs[b * HH + j] = hn;
                __nv_bfloat16 hh, hl;
                split_bf16(hn, hh, hl);
                int swo = ((seg ^ (b & 7)) << 4) + jsw * 2;
                *(__nv_bfloat16*)(sm + SA_OFF + b * 256 + swo)        = hh;
                *(__nv_bfloat16*)(sm + SA_OFF + (b + 8) * 256 + swo)  = hl;
                if (write_seq) {
                    size_t m = (size_t)((b0 + b) * TT + t) * HH + j;
                    seqh[m] = hh;
                    seql[m] = hl;
                }
            }
        }
        __syncthreads();
    }

    if (!write_seq && gtype == 2) {
#pragma unroll
        for (int b = 0; b < NB; b++)
            hlast_out[(b0 + b) * HH + j] = hs[b * HH + j];
    }
}

// ---------------------------------------------------------------------------
// head
// ---------------------------------------------------------------------------
__global__ __launch_bounds__(64)
void head_kernel(const float* __restrict__ hlast, const float* __restrict__ W1,
                 const float* __restrict__ b1, const float* __restrict__ W2,
                 const float* __restrict__ b2, float* __restrict__ out)
{
    __shared__ float hsm[HH];
    __shared__ float partial[2];
    const int b = blockIdx.x, tid = threadIdx.x;

    hsm[tid]      = hlast[b * HH + tid];
    hsm[tid + 64] = hlast[b * HH + 64 + tid];
    __syncthreads();

    float acc = b1[tid];
#pragma unroll 4
    for (int k = 0; k < HH; k++)
        acc += hsm[k] * W1[tid * HH + k];
    float v = fmaxf(acc, 0.f) * W2[tid];

#pragma unroll
    for (int o = 16; o > 0; o >>= 1)
        v += __shfl_down_sync(0xffffffffu, v, o);
    if ((tid & 31) == 0) partial[tid >> 5] = v;
    __syncthreads();
    if (tid == 0)
        out[b] = 1.f / (1.f + expf(-(partial[0] + partial[1] + b2[0])));
}

// ---------------------------------------------------------------------------
// Launch
// ---------------------------------------------------------------------------
extern "C" void kernel_launch(void* const* d_in, const int* in_sizes, int n_in,
                              void* d_out, int out_size)
{
    (void)in_sizes; (void)n_in; (void)out_size;
    const float* x     = (const float*)d_in[0];
    const float* W_ih0 = (const float*)d_in[1];
    const float* W_hh0 = (const float*)d_in[2];
    const float* b_ih0 = (const float*)d_in[3];
    const float* b_hh0 = (const float*)d_in[4];
    const float* W_ih1 = (const float*)d_in[5];
    const float* W_hh1 = (const float*)d_in[6];
    const float* b_ih1 = (const float*)d_in[7];
    const float* b_hh1 = (const float*)d_in[8];
    const float* W1    = (const float*)d_in[9];
    const float* b1    = (const float*)d_in[10];
    const float* W2    = (const float*)d_in[11];
    const float* b2    = (const float*)d_in[12];
    float* out = (float*)d_out;

    float *gi, *hlast;
    __nv_bfloat16 *xh, *xl, *sh, *sl, *w0h, *w0l, *w1h, *w1l;
    cudaGetSymbolAddress((void**)&gi,    g_gi);
    cudaGetSymbolAddress((void**)&hlast, g_hlast);
    cudaGetSymbolAddress((void**)&xh,  g_xh);
    cudaGetSymbolAddress((void**)&xl,  g_xl);
    cudaGetSymbolAddress((void**)&sh,  g_sh);
    cudaGetSymbolAddress((void**)&sl,  g_sl);
    cudaGetSymbolAddress((void**)&w0h, g_w0h);
    cudaGetSymbolAddress((void**)&w0l, g_w0l);
    cudaGetSymbolAddress((void**)&w1h, g_w1h);
    cudaGetSymbolAddress((void**)&w1l, g_w1l);

    cudaFuncSetAttribute(gru_layer_tc, cudaFuncAttributeMaxDynamicSharedMemorySize,
                         GRU_SMEM);
    cudaFuncSetAttribute(gemm_tc3, cudaFuncAttributeMaxDynamicSharedMemorySize,
                         GEMM_SMEM);

    dim3 tgrid(G3 / 128, MTOT / 128);   // (3, 2048): n-blocks adjacent -> A L2 reuse

    prep_split_rows<<<MTOT / 8, 256>>>(x, xh, xl, MTOT, II, KP0);
    prep_split_rows<<<G3 / 8, 256>>>(W_ih0, w0h, w0l, G3, II, KP0);
    prep_split_rows<<<G3 / 8, 256>>>(W_ih1, w1h, w1l, G3, HH, HH);

    gemm_tc3<<<tgrid, 256, GEMM_SMEM>>>(xh, xl, w0h, w0l, b_ih0, gi, KP0);
    gru_layer_tc<<<BATCH / NB, GNTH, GRU_SMEM>>>(gi, W_hh0, b_hh0, sh, sl, nullptr, 1);
    gemm_tc3<<<tgrid, 256, GEMM_SMEM>>>(sh, sl, w1h, w1l, b_ih1, gi, HH);
    gru_layer_tc<<<BATCH / NB, GNTH, GRU_SMEM>>>(gi, W_hh1, b_hh1, nullptr, nullptr, hlast, 0);
    head_kernel<<<BATCH, 64>>>(hlast, W1, b1, W2, b2, out);
}